// round 6
// baseline (speedup 1.0000x reference)
#include <cuda_runtime.h>
#include <math.h>

#define BATCH  8
#define CH     192
#define C3     576
#define NVOX   13824       // 24*24*24
#define HEADS  6
#define HD     32
#define EPSN   1e-12f

// Scratch
__device__ float g_Z[(size_t)BATCH * CH * NVOX];     // Z = Gw @ X (only q/k cols valid)
__device__ float g_V[(size_t)BATCH * NVOX * CH];     // Vbuf
__device__ float g_Gw[CH * CH];
__device__ float g_wb[CH];
__device__ float g_pwT[CH * CH];
__device__ float g_c[4];                             // [0] = b2
__device__ float g_spart[BATCH * HEADS * 6 * 1152];
__device__ float g_attn[BATCH * HEADS * HD * HD];
__device__ float g_M[BATCH * CH * CH];

// MMA-fragment-layout A buffers (tf32 bits). Layout:
//   frag[((c * rtiles + R) * 32 + lane) * 4 + {0..3}]
//   {A[R16+gid][c8+t4], A[R16+gid+8][c8+t4], A[R16+gid][c8+t4+4], A[R16+gid+8][c8+t4+4]}
__device__ unsigned g_GwF[24 * 12 * 32 * 4];
__device__ unsigned g_WF [24 * 36 * 32 * 4];
__device__ unsigned g_MF [BATCH * 24 * 12 * 32 * 4];

// ---------------------------------------------------------------------------
__device__ __forceinline__ unsigned f2tf(float f) {
    unsigned u;
    asm("cvt.rna.tf32.f32 %0, %1;" : "=r"(u) : "f"(f));
    return u;
}
__device__ __forceinline__ void mma_tf32(float* c, const unsigned* a, const unsigned* b) {
    asm volatile(
        "mma.sync.aligned.m16n8k8.row.col.f32.tf32.tf32.f32 "
        "{%0,%1,%2,%3},{%4,%5,%6,%7},{%8,%9},{%0,%1,%2,%3};"
        : "+f"(c[0]), "+f"(c[1]), "+f"(c[2]), "+f"(c[3])
        : "r"(a[0]), "r"(a[1]), "r"(a[2]), "r"(a[3]), "r"(b[0]), "r"(b[1]));
}

// ---------------------------------------------------------------------------
// K0a: Gw = W^T W
// ---------------------------------------------------------------------------
__global__ __launch_bounds__(256) void gw_kernel(const float* __restrict__ w)
{
    __shared__ float Wi[32][33];
    __shared__ float Wj[32][33];
    const int i0 = blockIdx.x * 32, j0 = blockIdx.y * 32;
    const int t = threadIdx.x;
    const int ti = t & 31, tj = (t >> 5) * 4;
    float acc[4] = {0.f, 0.f, 0.f, 0.f};

    for (int a0 = 0; a0 < C3; a0 += 32) {
        __syncthreads();
#pragma unroll
        for (int l = 0; l < 4; l++) {
            const int a = (t >> 5) + 8 * l, c = t & 31;
            Wi[a][c] = w[(a0 + a) * CH + i0 + c];
            Wj[a][c] = w[(a0 + a) * CH + j0 + c];
        }
        __syncthreads();
#pragma unroll
        for (int a = 0; a < 32; a++) {
            const float wi = Wi[a][ti];
#pragma unroll
            for (int r = 0; r < 4; r++) acc[r] += wi * Wj[a][tj + r];
        }
    }
#pragma unroll
    for (int r = 0; r < 4; r++) g_Gw[(i0 + ti) * CH + j0 + tj + r] = acc[r];
}

// K0b: wb = W^T beta; b2 = sum beta^2.
__global__ __launch_bounds__(256) void wb_kernel(const float* __restrict__ w,
                                                 const float* __restrict__ beta)
{
    __shared__ float red[64];
    const int t = threadIdx.x;
    if (t < CH) {
        float s = 0.f;
        for (int a = 0; a < C3; a++) s += beta[a] * w[a * CH + t];
        g_wb[t] = s;
    }
    if (t < 64) {
        float p = 0.f;
        for (int a = t; a < C3; a += 64) p += beta[a] * beta[a];
        red[t] = p;
    }
    __syncthreads();
    if (t == 0) {
        float s = 0.f;
        for (int i = 0; i < 64; i++) s += red[i];
        g_c[0] = s;
    }
}

// K0c: pwT[c][o] = proj_w[o][c]
__global__ __launch_bounds__(256) void ptrans_kernel(const float* __restrict__ pw)
{
    __shared__ float tile[32][33];
    const int bx = blockIdx.x * 32, by = blockIdx.y * 32;
    const int tx = threadIdx.x & 31, ty = threadIdx.x >> 5;
#pragma unroll
    for (int l = 0; l < 4; l++)
        tile[ty + 8 * l][tx] = pw[(by + ty + 8 * l) * CH + bx + tx];
    __syncthreads();
#pragma unroll
    for (int l = 0; l < 4; l++)
        g_pwT[(bx + ty + 8 * l) * CH + by + tx] = tile[tx][ty + 8 * l];
}

// ---------------------------------------------------------------------------
// K0d: convert a row-major [rtiles*16 x 192] fp32 matrix to fragment layout.
// grid (rtiles, nmat), 256 thr.
// ---------------------------------------------------------------------------
__global__ __launch_bounds__(256) void fragify(const float* __restrict__ src,
                                               unsigned* __restrict__ dst,
                                               int rtiles)
{
    const int R = blockIdx.x;
    const size_t m = blockIdx.y;
    src += m * (size_t)(CH * CH);
    dst += m * (size_t)(24 * 12 * 32 * 4);
    const int t = threadIdx.x;
    const int l = t & 31;
    const int row = R * 16 + (l >> 2);
    const int colb = l & 3;
    for (int c = t >> 5; c < 24; c += 8) {
        const int col = c * 8 + colb;
        uint4 v;
        v.x = f2tf(src[row * CH + col]);
        v.y = f2tf(src[(row + 8) * CH + col]);
        v.z = f2tf(src[row * CH + col + 4]);
        v.w = f2tf(src[(row + 8) * CH + col + 4]);
        *(uint4*)(dst + (size_t)((c * rtiles + R) * 32 + l) * 4) = v;
    }
}

// ---------------------------------------------------------------------------
// K1: Z[b] = Gw @ X[b], ONLY columns 576e + [0,384).
// BM=192, BN=192, BK=16, 384 thr, 12 warps (4m x 3n), warp 48x64.
// A fragments straight from gmem (g_GwF); B double-buffered in smem.
// ---------------------------------------------------------------------------
__global__ __launch_bounds__(384, 1) void z_gemm(const float* __restrict__ x)
{
    __shared__ unsigned Bs[2][16 * 200];

    const int b  = blockIdx.z;
    const int n0 = 576 * (blockIdx.x >> 1) + 192 * (blockIdx.x & 1);
    const int t  = threadIdx.x;
    const int wid = t >> 5, lane = t & 31;
    const int wm = wid & 3, wn = wid >> 2;
    const int gid = lane >> 2, tid4 = lane & 3;

    const float* xb = x + (size_t)b * CH * NVOX;
    float* zb = g_Z + (size_t)b * CH * NVOX;
    const uint4* aF = (const uint4*)g_GwF;

    float acc[3][8][4];
#pragma unroll
    for (int i = 0; i < 3; i++)
#pragma unroll
        for (int j = 0; j < 8; j++)
#pragma unroll
            for (int e = 0; e < 4; e++) acc[i][j][e] = 0.f;

    const int brow = t / 48;          // 0..7 (+8 for second load)
    const int bcol = (t % 48) * 4;

    float4 br[2];
#define LDB_Z(K0) { br[0] = *(const float4*)(xb + (size_t)((K0) + brow) * NVOX + n0 + bcol); \
                    br[1] = *(const float4*)(xb + (size_t)((K0) + 8 + brow) * NVOX + n0 + bcol); }
#define STB_Z(ST) { uint4 u0 = make_uint4(f2tf(br[0].x), f2tf(br[0].y), f2tf(br[0].z), f2tf(br[0].w)); \
                    uint4 u1 = make_uint4(f2tf(br[1].x), f2tf(br[1].y), f2tf(br[1].z), f2tf(br[1].w)); \
                    *(uint4*)&Bs[ST][brow * 200 + bcol] = u0; \
                    *(uint4*)&Bs[ST][(brow + 8) * 200 + bcol] = u1; }

    LDB_Z(0);
    STB_Z(0);
    LDB_Z(16);
    __syncthreads();

    for (int it = 0; it < 12; it++) {
        const int st = it & 1;
        if (it < 11) { STB_Z(st ^ 1); }
        if (it < 10) { LDB_Z(16 * (it + 2)); }

        uint4 afr[3][2];
        const int c0 = it * 2;
#pragma unroll
        for (int mt = 0; mt < 3; mt++) {
            const int R = wm * 3 + mt;
            afr[mt][0] = aF[(size_t)((c0)*12 + R) * 32 + lane];
            afr[mt][1] = aF[(size_t)((c0 + 1) * 12 + R) * 32 + lane];
        }
#pragma unroll
        for (int h = 0; h < 2; h++) {
            const int kk = h * 8;
            unsigned bf[8][2];
#pragma unroll
            for (int nt = 0; nt < 8; nt++) {
                const int col = wn * 64 + nt * 8 + gid;
                bf[nt][0] = Bs[st][(kk + tid4) * 200 + col];
                bf[nt][1] = Bs[st][(kk + tid4 + 4) * 200 + col];
            }
#pragma unroll
            for (int mt = 0; mt < 3; mt++)
#pragma unroll
                for (int nt = 0; nt < 8; nt++)
                    mma_tf32(acc[mt][nt], (const unsigned*)&afr[mt][h], bf[nt]);
        }
        __syncthreads();
    }

#pragma unroll
    for (int mt = 0; mt < 3; mt++) {
        const int r0 = wm * 48 + mt * 16 + gid;
#pragma unroll
        for (int nt = 0; nt < 8; nt++) {
            const int col = n0 + wn * 64 + nt * 8 + 2 * tid4;
            *(float2*)(zb + (size_t)r0 * NVOX + col) = make_float2(acc[mt][nt][0], acc[mt][nt][1]);
            *(float2*)(zb + (size_t)(r0 + 8) * NVOX + col) = make_float2(acc[mt][nt][2], acc[mt][nt][3]);
        }
    }
}

// ---------------------------------------------------------------------------
// K2: Vbuf. A = qkv_w (frag, 36 row-tiles), B cols 576e+384+[0,192).
// ---------------------------------------------------------------------------
__global__ __launch_bounds__(384, 1) void v_gemm(const float* __restrict__ x,
                                                 const float* __restrict__ beta)
{
    __shared__ unsigned Bs[2][16 * 200];

    const int b  = blockIdx.z;
    const int e  = blockIdx.x;
    const int m0 = blockIdx.y * 192;
    const int t  = threadIdx.x;
    const int wid = t >> 5, lane = t & 31;
    const int wm = wid & 3, wn = wid >> 2;
    const int gid = lane >> 2, tid4 = lane & 3;

    const float* xb = x + (size_t)b * CH * NVOX + 576 * e + 384;
    float* vb = g_V + (size_t)b * NVOX * CH;
    const uint4* aF = (const uint4*)g_WF;
    const int Rb = (m0 >> 4);

    float acc[3][8][4];
#pragma unroll
    for (int i = 0; i < 3; i++)
#pragma unroll
        for (int j = 0; j < 8; j++)
#pragma unroll
            for (int q = 0; q < 4; q++) acc[i][q > 3 ? 0 : j][q] = 0.f;  // placeholder
#pragma unroll
    for (int i = 0; i < 3; i++)
#pragma unroll
        for (int j = 0; j < 8; j++)
#pragma unroll
            for (int q = 0; q < 4; q++) acc[i][j][q] = 0.f;

    const int brow = t / 48;
    const int bcol = (t % 48) * 4;

    float4 br[2];
#define LDB_V(K0) { br[0] = *(const float4*)(xb + (size_t)((K0) + brow) * NVOX + bcol); \
                    br[1] = *(const float4*)(xb + (size_t)((K0) + 8 + brow) * NVOX + bcol); }

    LDB_V(0);
    STB_Z(0);
    LDB_V(16);
    __syncthreads();

    for (int it = 0; it < 12; it++) {
        const int st = it & 1;
        if (it < 11) { STB_Z(st ^ 1); }
        if (it < 10) { LDB_V(16 * (it + 2)); }

        uint4 afr[3][2];
        const int c0 = it * 2;
#pragma unroll
        for (int mt = 0; mt < 3; mt++) {
            const int R = Rb + wm * 3 + mt;
            afr[mt][0] = aF[(size_t)((c0)*36 + R) * 32 + lane];
            afr[mt][1] = aF[(size_t)((c0 + 1) * 36 + R) * 32 + lane];
        }
#pragma unroll
        for (int h = 0; h < 2; h++) {
            const int kk = h * 8;
            unsigned bf[8][2];
#pragma unroll
            for (int nt = 0; nt < 8; nt++) {
                const int col = wn * 64 + nt * 8 + gid;
                bf[nt][0] = Bs[st][(kk + tid4) * 200 + col];
                bf[nt][1] = Bs[st][(kk + tid4 + 4) * 200 + col];
            }
#pragma unroll
            for (int mt = 0; mt < 3; mt++)
#pragma unroll
                for (int nt = 0; nt < 8; nt++)
                    mma_tf32(acc[mt][nt], (const unsigned*)&afr[mt][h], bf[nt]);
        }
        __syncthreads();
    }

#pragma unroll
    for (int mt = 0; mt < 3; mt++) {
        const int r0 = m0 + wm * 48 + mt * 16 + gid;
        const float b0 = beta[r0], b1 = beta[r0 + 8];
#pragma unroll
        for (int nt = 0; nt < 8; nt++) {
            const int pc = e * 192 + wn * 64 + nt * 8 + 2 * tid4;
            *(float2*)(vb + (size_t)r0 * 4608 + pc) =
                make_float2(acc[mt][nt][0] + b0, acc[mt][nt][1] + b0);
            *(float2*)(vb + (size_t)(r0 + 8) * 4608 + pc) =
                make_float2(acc[mt][nt][2] + b1, acc[mt][nt][3] + b1);
        }
    }
}

// ---------------------------------------------------------------------------
// K3: score partials, float4 loads, double-buffered e-loop.
// ---------------------------------------------------------------------------
__global__ __launch_bounds__(256) void scores_kernel(const float* __restrict__ x)
{
    __shared__ float Xq[2][32][36], Zq[2][32][36], Xk[2][32][36], Zk[2][32][36];
    __shared__ float wbs[32];

    const int isl = blockIdx.x, h = blockIdx.y, b = blockIdx.z;
    const int i0  = isl * 32;
    const int t   = threadIdx.x;
    const int h32 = h * 32;

    const float* xb = x + (size_t)b * CH * NVOX;
    const float* zb = g_Z + (size_t)b * CH * NVOX;

    if (t < 32) wbs[t] = g_wb[i0 + t];

    const int li  = t >> 3;
    const int lc4 = (t & 7) << 2;
    const int cc  = t >> 3;
    const int d0  = (t & 7) << 2;

    float s[4] = {0.f, 0.f, 0.f, 0.f};
    float dac = 0.f, wac = 0.f;

    const size_t rowoff = (size_t)(i0 + li) * NVOX;
    float4 rq, rzq, rk, rzk;
    {
        const int u = h32 + lc4;
        rq  = *(const float4*)(xb + rowoff + u);
        rzq = *(const float4*)(zb + rowoff + u);
        rk  = *(const float4*)(xb + rowoff + u + 192);
        rzk = *(const float4*)(zb + rowoff + u + 192);
    }
    *(float4*)&Xq[0][li][lc4] = rq;  *(float4*)&Zq[0][li][lc4] = rzq;
    *(float4*)&Xk[0][li][lc4] = rk;  *(float4*)&Zk[0][li][lc4] = rzk;
    __syncthreads();

    for (int e = 0; e < 24; e++) {
        const int cur = e & 1, nxt = cur ^ 1;
        if (e < 23) {
            const int u = 576 * (e + 1) + h32 + lc4;
            rq  = *(const float4*)(xb + rowoff + u);
            rzq = *(const float4*)(zb + rowoff + u);
            rk  = *(const float4*)(xb + rowoff + u + 192);
            rzk = *(const float4*)(zb + rowoff + u + 192);
        }
#pragma unroll
        for (int i = 0; i < 32; i++) {
            const float qv = Xq[cur][i][cc];
            const float4 zv = *(const float4*)&Zk[cur][i][d0];
            s[0] += qv * zv.x; s[1] += qv * zv.y; s[2] += qv * zv.z; s[3] += qv * zv.w;
        }
        if (t < 32) {
#pragma unroll
            for (int i = 0; i < 32; i++) {
                const float xv = Xq[cur][i][t];
                dac += xv * Zq[cur][i][t];
                wac += wbs[i] * xv;
            }
        } else if (t < 64) {
            const int c = t - 32;
#pragma unroll
            for (int i = 0; i < 32; i++) {
                const float xv = Xk[cur][i][c];
                dac += xv * Zk[cur][i][c];
                wac += wbs[i] * xv;
            }
        }
        if (e < 23) {
            *(float4*)&Xq[nxt][li][lc4] = rq;  *(float4*)&Zq[nxt][li][lc4] = rzq;
            *(float4*)&Xk[nxt][li][lc4] = rk;  *(float4*)&Zk[nxt][li][lc4] = rzk;
        }
        __syncthreads();
    }

    float* sp = g_spart + (size_t)((b * HEADS + h) * 6 + isl) * 1152;
    sp[cc * 32 + d0 + 0] = s[0];
    sp[cc * 32 + d0 + 1] = s[1];
    sp[cc * 32 + d0 + 2] = s[2];
    sp[cc * 32 + d0 + 3] = s[3];
    if (t < 32)       { sp[1024 + t] = dac; sp[1088 + t] = wac; }
    else if (t < 64)  { sp[1056 + (t - 32)] = dac; sp[1120 + (t - 32)] = wac; }
}

// ---------------------------------------------------------------------------
// K4: reduce partials, assemble S + bias terms, normalize, softmax -> attn
// ---------------------------------------------------------------------------
__global__ __launch_bounds__(256) void softmax_kernel(const float* __restrict__ temp)
{
    __shared__ float sS[1024];
    __shared__ float snq[32], snk[32], swq[32], swk[32];

    const int h = blockIdx.x, b = blockIdx.y;
    const int t = threadIdx.x;
    const float b2 = g_c[0];
    const float* sp = g_spart + (size_t)((b * HEADS + h) * 6) * 1152;

#pragma unroll
    for (int i = 0; i < 4; i++) {
        const int e = t + i * 256;
        float a = 0.f;
        for (int s = 0; s < 6; s++) a += sp[s * 1152 + e];
        sS[e] = a;
    }
    if (t < 64) {
        float d = 0.f, wv = 0.f;
        const int od = 1024 + t, ow = 1088 + t;
        for (int s = 0; s < 6; s++) { d += sp[s * 1152 + od]; wv += sp[s * 1152 + ow]; }
        const float n2 = d + 2.f * wv + 24.f * b2;
        const float r = fmaxf(sqrtf(fmaxf(n2, 0.f)), EPSN);
        if (t < 32) { snq[t] = r; swq[t] = wv; }
        else        { snk[t - 32] = r; swk[t - 32] = wv; }
    }
    __syncthreads();

    const int w = t >> 5, lane = t & 31;
    const float tv = temp[h];
    float* ab = g_attn + (size_t)((b * HEADS + h) * HD) * HD;

    for (int r = 0; r < 4; r++) {
        const int c = w * 4 + r;
        const float Sfull = sS[c * 32 + lane] + swq[c] + swk[lane] + 24.f * b2;
        float L = Sfull / (snq[c] * snk[lane]) * tv;
        float mx = L;
#pragma unroll
        for (int o = 16; o > 0; o >>= 1) mx = fmaxf(mx, __shfl_xor_sync(0xffffffffu, mx, o));
        const float ev = expf(L - mx);
        float sm = ev;
#pragma unroll
        for (int o = 16; o > 0; o >>= 1) sm += __shfl_xor_sync(0xffffffffu, sm, o);
        ab[c * 32 + lane] = ev / sm;
    }
}

// ---------------------------------------------------------------------------
// K5: M[b][o][h*32+d] = sum_cc pwT[cc*6+h][o] * attn[b,h,cc,d]
// ---------------------------------------------------------------------------
__global__ __launch_bounds__(192) void mmix_kernel()
{
    __shared__ float att[32][33];
    const int h = blockIdx.x, b = blockIdx.y;
    const int t = threadIdx.x;

    const float* ab = g_attn + (size_t)((b * HEADS + h) * HD) * HD;
    for (int e = t; e < 1024; e += 192) att[e >> 5][e & 31] = ab[e];
    __syncthreads();

    float pwr[32];
#pragma unroll
    for (int cc = 0; cc < 32; cc++) pwr[cc] = g_pwT[(cc * HEADS + h) * CH + t];

    float* Mb = g_M + (size_t)b * CH * CH + t * CH + h * HD;
#pragma unroll 4
    for (int d = 0; d < 32; d++) {
        float s = 0.f;
#pragma unroll
        for (int cc = 0; cc < 32; cc++) s += pwr[cc] * att[cc][d];
        Mb[d] = s;
    }
}

// ---------------------------------------------------------------------------
// K6: y[b] = M[b] @ Vbuf[b]^T + proj_b.  A frag from g_MF, B double-buffered.
// BM=192, BN=192, 384 thr, warp 48x64.
// ---------------------------------------------------------------------------
__global__ __launch_bounds__(384, 1) void out_gemm(float* __restrict__ y,
                                                   const float* __restrict__ pbias)
{
    __shared__ unsigned Bs[2][192 * 20];

    const int b  = blockIdx.z;
    const int n0 = blockIdx.x * 192;
    const int t  = threadIdx.x;
    const int wid = t >> 5, lane = t & 31;
    const int wm = wid & 3, wn = wid >> 2;
    const int gid = lane >> 2, tid4 = lane & 3;

    const float* vb = g_V + (size_t)b * NVOX * CH;
    float* yb = y + (size_t)b * CH * NVOX;
    const uint4* aF = (const uint4*)g_MF + (size_t)b * (24 * 12 * 32);

    float acc[3][8][4];
#pragma unroll
    for (int i = 0; i < 3; i++)
#pragma unroll
        for (int j = 0; j < 8; j++)
#pragma unroll
            for (int e = 0; e < 4; e++) acc[i][j][e] = 0.f;

    const int on = t >> 2, okq = (t & 3) * 4;

    float4 br[2];
#define LDB_O(K0) { br[0] = *(const float4*)(vb + (size_t)(n0 + on) * CH + (K0) + okq); \
                    br[1] = *(const float4*)(vb + (size_t)(n0 + 96 + on) * CH + (K0) + okq); }
#define STB_O(ST) { uint4 u0 = make_uint4(f2tf(br[0].x), f2tf(br[0].y), f2tf(br[0].z), f2tf(br[0].w)); \
                    uint4 u1 = make_uint4(f2tf(br[1].x), f2tf(br[1].y), f2tf(br[1].z), f2tf(br[1].w)); \
                    *(uint4*)&Bs[ST][on * 20 + okq] = u0; \
                    *(uint4*)&Bs[ST][(on + 96) * 20 + okq] = u1; }

    LDB_O(0);
    STB_O(0);
    LDB_O(16);
    __syncthreads();

    for (int it = 0; it < 12; it++) {
        const int st = it & 1;
        if (it < 11) { STB_O(st ^ 1); }
        if (it < 10) { LDB_O(16 * (it + 2)); }

        uint4 afr[3][2];
        const int c0 = it * 2;
#pragma unroll
        for (int mt = 0; mt < 3; mt++) {
            const int R = wm * 3 + mt;
            afr[mt][0] = aF[(size_t)((c0)*12 + R) * 32 + lane];
            afr[mt][1] = aF[(size_t)((c0 + 1) * 12 + R) * 32 + lane];
        }
#pragma unroll
        for (int h = 0; h < 2; h++) {
            const int kk = h * 8;
            unsigned bf[8][2];
#pragma unroll
            for (int nt = 0; nt < 8; nt++) {
                const int col = wn * 64 + nt * 8 + gid;
                bf[nt][0] = Bs[st][col * 20 + kk + tid4];
                bf[nt][1] = Bs[st][col * 20 + kk + tid4 + 4];
            }
#pragma unroll
            for (int mt = 0; mt < 3; mt++)
#pragma unroll
                for (int nt = 0; nt < 8; nt++)
                    mma_tf32(acc[mt][nt], (const unsigned*)&afr[mt][h], bf[nt]);
        }
        __syncthreads();
    }

#pragma unroll
    for (int mt = 0; mt < 3; mt++) {
        const int r0 = wm * 48 + mt * 16 + gid;
        const float b0 = pbias[r0], b1 = pbias[r0 + 8];
#pragma unroll
        for (int nt = 0; nt < 8; nt++) {
            const int col = n0 + wn * 64 + nt * 8 + 2 * tid4;
            *(float2*)(yb + (size_t)r0 * NVOX + col) =
                make_float2(acc[mt][nt][0] + b0, acc[mt][nt][1] + b0);
            *(float2*)(yb + (size_t)(r0 + 8) * NVOX + col) =
                make_float2(acc[mt][nt][2] + b1, acc[mt][nt][3] + b1);
        }
    }
}

// ---------------------------------------------------------------------------
extern "C" void kernel_launch(void* const* d_in, const int* in_sizes, int n_in,
                              void* d_out, int out_size)
{
    const float* x      = (const float*)d_in[0];
    const float* qkv_w  = (const float*)d_in[1];
    const float* qkv_b  = (const float*)d_in[2];
    const float* temp   = (const float*)d_in[3];
    const float* proj_w = (const float*)d_in[4];
    const float* proj_b = (const float*)d_in[5];
    float* y = (float*)d_out;

    gw_kernel     <<<dim3(6, 6), 256>>>(qkv_w);
    wb_kernel     <<<1, 256>>>(qkv_w, qkv_b);
    ptrans_kernel <<<dim3(6, 6), 256>>>(proj_w);

    // fragment-layout prepasses
    {
        unsigned* gwF; cudaGetSymbolAddress((void**)&gwF, g_GwF);
        unsigned* wF;  cudaGetSymbolAddress((void**)&wF,  g_WF);
        float* gw;     cudaGetSymbolAddress((void**)&gw,  g_Gw);
        fragify <<<dim3(12, 1), 256>>>(gw, gwF, 12);
        fragify <<<dim3(36, 1), 256>>>(qkv_w, wF, 36);
    }

    z_gemm        <<<dim3(48, 1, BATCH), 384>>>(x);
    v_gemm        <<<dim3(24, 3, BATCH), 384>>>(x, qkv_b);
    scores_kernel <<<dim3(6, HEADS, BATCH), 256>>>(x);
    softmax_kernel<<<dim3(HEADS, BATCH), 256>>>(temp);
    mmix_kernel   <<<dim3(HEADS, BATCH), 192>>>();

    {
        unsigned* mF; cudaGetSymbolAddress((void**)&mF, g_MF);
        float* m;     cudaGetSymbolAddress((void**)&m,  g_M);
        fragify <<<dim3(12, BATCH), 256>>>(m, mF, 12);
    }

    out_gemm      <<<dim3(72, 1, BATCH), 384>>>(y, proj_b);
}

// round 7
// speedup vs baseline: 1.0570x; 1.0570x over previous
#include <cuda_runtime.h>
#include <math.h>

#define BATCH  8
#define CH     192
#define C3     576
#define NVOX   13824       // 24*24*24
#define HEADS  6
#define HD     32
#define EPSN   1e-12f

// Scratch
__device__ float g_Z[(size_t)BATCH * CH * NVOX];     // Z = Gw @ X (only q/k cols valid)
__device__ float g_V[(size_t)BATCH * NVOX * CH];     // Vbuf
__device__ float g_Gw[CH * CH];
__device__ float g_wb[CH];
__device__ float g_pwT[CH * CH];
__device__ float g_c[4];                             // [0] = b2
__device__ float g_spart[BATCH * HEADS * 6 * 1152];
__device__ float g_attn[BATCH * HEADS * HD * HD];
__device__ float g_M[BATCH * CH * CH];

// ---------------------------------------------------------------------------
__device__ __forceinline__ unsigned f2tf(float f) {
    unsigned u;
    asm("cvt.rna.tf32.f32 %0, %1;" : "=r"(u) : "f"(f));
    return u;
}
__device__ __forceinline__ void mma_tf32(float* c, const unsigned* a, const unsigned* b) {
    asm volatile(
        "mma.sync.aligned.m16n8k8.row.col.f32.tf32.tf32.f32 "
        "{%0,%1,%2,%3},{%4,%5,%6,%7},{%8,%9},{%0,%1,%2,%3};"
        : "+f"(c[0]), "+f"(c[1]), "+f"(c[2]), "+f"(c[3])
        : "r"(a[0]), "r"(a[1]), "r"(a[2]), "r"(a[3]), "r"(b[0]), "r"(b[1]));
}

// ---------------------------------------------------------------------------
// K0a: Gw = W^T W
// ---------------------------------------------------------------------------
__global__ __launch_bounds__(256) void gw_kernel(const float* __restrict__ w)
{
    __shared__ float Wi[32][33];
    __shared__ float Wj[32][33];
    const int i0 = blockIdx.x * 32, j0 = blockIdx.y * 32;
    const int t = threadIdx.x;
    const int ti = t & 31, tj = (t >> 5) * 4;
    float acc[4] = {0.f, 0.f, 0.f, 0.f};

    for (int a0 = 0; a0 < C3; a0 += 32) {
        __syncthreads();
#pragma unroll
        for (int l = 0; l < 4; l++) {
            const int a = (t >> 5) + 8 * l, c = t & 31;
            Wi[a][c] = w[(a0 + a) * CH + i0 + c];
            Wj[a][c] = w[(a0 + a) * CH + j0 + c];
        }
        __syncthreads();
#pragma unroll
        for (int a = 0; a < 32; a++) {
            const float wi = Wi[a][ti];
#pragma unroll
            for (int r = 0; r < 4; r++) acc[r] += wi * Wj[a][tj + r];
        }
    }
#pragma unroll
    for (int r = 0; r < 4; r++) g_Gw[(i0 + ti) * CH + j0 + tj + r] = acc[r];
}

// K0b: wb = W^T beta; b2 = sum beta^2.
__global__ __launch_bounds__(256) void wb_kernel(const float* __restrict__ w,
                                                 const float* __restrict__ beta)
{
    __shared__ float red[64];
    const int t = threadIdx.x;
    if (t < CH) {
        float s = 0.f;
        for (int a = 0; a < C3; a++) s += beta[a] * w[a * CH + t];
        g_wb[t] = s;
    }
    if (t < 64) {
        float p = 0.f;
        for (int a = t; a < C3; a += 64) p += beta[a] * beta[a];
        red[t] = p;
    }
    __syncthreads();
    if (t == 0) {
        float s = 0.f;
        for (int i = 0; i < 64; i++) s += red[i];
        g_c[0] = s;
    }
}

// K0c: pwT[c][o] = proj_w[o][c]
__global__ __launch_bounds__(256) void ptrans_kernel(const float* __restrict__ pw)
{
    __shared__ float tile[32][33];
    const int bx = blockIdx.x * 32, by = blockIdx.y * 32;
    const int tx = threadIdx.x & 31, ty = threadIdx.x >> 5;
#pragma unroll
    for (int l = 0; l < 4; l++)
        tile[ty + 8 * l][tx] = pw[(by + ty + 8 * l) * CH + bx + tx];
    __syncthreads();
#pragma unroll
    for (int l = 0; l < 4; l++)
        g_pwT[(bx + ty + 8 * l) * CH + by + tx] = tile[tx][ty + 8 * l];
}

// ---------------------------------------------------------------------------
// K1: fused Z-gemm + V-gemm. 960 blocks:
//  bid < 384: Z[b] = Gw @ X[b] at columns 576e + [0,384)   (b=bid/48)
//  bid >=384: Vbuf = W[m0:m0+192] @ X-vcols(e) + beta
// BM=192, BN=192, BK=16, 384 thr, 12 warps (4m x 3n), warp 48x64.
// A,B double-buffered in dynamic smem, one barrier per k-iter.
// ---------------------------------------------------------------------------
__global__ __launch_bounds__(384, 1) void zv_gemm(const float* __restrict__ x,
                                                  const float* __restrict__ qkv_w,
                                                  const float* __restrict__ beta)
{
    extern __shared__ unsigned smw[];
    unsigned* AS = smw;               // stage s at s*3840  (192*20)
    unsigned* BS = smw + 7680;        // stage s at s*3200  (16*200)

    const int bid = blockIdx.x;
    const bool isZ = bid < 384;

    int b, e = 0, n0 = 0, m0 = 0;
    const float* Asrc;
    const float* bsrc;
    if (isZ) {
        b = bid / 48;
        const int sub = bid % 48;
        n0 = 576 * (sub >> 1) + 192 * (sub & 1);
        Asrc = g_Gw;
        bsrc = x + (size_t)b * CH * NVOX + n0;
    } else {
        const int r = bid - 384;
        b = r / 72;
        const int r2 = r % 72;
        e  = r2 % 24;
        m0 = (r2 / 24) * 192;
        Asrc = qkv_w + (size_t)m0 * CH;
        bsrc = x + (size_t)b * CH * NVOX + 576 * e + 384;
    }

    const int t = threadIdx.x;
    const int wid = t >> 5, lane = t & 31;
    const int wm = wid & 3, wn = wid >> 2;
    const int gid = lane >> 2, tid4 = lane & 3;

    float acc[3][8][4];
#pragma unroll
    for (int i = 0; i < 3; i++)
#pragma unroll
        for (int j = 0; j < 8; j++)
#pragma unroll
            for (int q = 0; q < 4; q++) acc[i][j][q] = 0.f;

    const int arow0 = t >> 2, akq = (t & 3) * 4;   // rows arow0, arow0+96
    const int brow = t / 48;                        // 0..7 (+8)
    const int bcol = (t % 48) * 4;

    float4 ar0, ar1, br0, br1;
#define LDAB(K0) { ar0 = *(const float4*)(Asrc + (size_t)arow0 * CH + (K0) + akq);          \
                   ar1 = *(const float4*)(Asrc + (size_t)(arow0 + 96) * CH + (K0) + akq);   \
                   br0 = *(const float4*)(bsrc + (size_t)((K0) + brow) * NVOX + bcol);      \
                   br1 = *(const float4*)(bsrc + (size_t)((K0) + 8 + brow) * NVOX + bcol); }
#define STAB(ST) { unsigned* a0 = AS + (ST) * 3840 + arow0 * 20 + akq;                       \
                   a0[0]=f2tf(ar0.x); a0[1]=f2tf(ar0.y); a0[2]=f2tf(ar0.z); a0[3]=f2tf(ar0.w);\
                   unsigned* a1 = AS + (ST) * 3840 + (arow0 + 96) * 20 + akq;                \
                   a1[0]=f2tf(ar1.x); a1[1]=f2tf(ar1.y); a1[2]=f2tf(ar1.z); a1[3]=f2tf(ar1.w);\
                   unsigned* b0 = BS + (ST) * 3200 + brow * 200 + bcol;                      \
                   b0[0]=f2tf(br0.x); b0[1]=f2tf(br0.y); b0[2]=f2tf(br0.z); b0[3]=f2tf(br0.w);\
                   unsigned* b1 = BS + (ST) * 3200 + (brow + 8) * 200 + bcol;                \
                   b1[0]=f2tf(br1.x); b1[1]=f2tf(br1.y); b1[2]=f2tf(br1.z); b1[3]=f2tf(br1.w); }

    LDAB(0);
    STAB(0);
    LDAB(16);
    __syncthreads();

    for (int it = 0; it < 12; it++) {
        const int st = it & 1;
        if (it < 11) { STAB(st ^ 1); }
        if (it < 10) { LDAB(16 * (it + 2)); }

        const unsigned* As = AS + st * 3840;
        const unsigned* Bs = BS + st * 3200;
#pragma unroll
        for (int h = 0; h < 2; h++) {
            const int kk = h * 8;
            unsigned af[3][4], bf[8][2];
#pragma unroll
            for (int mt = 0; mt < 3; mt++) {
                const int row = wm * 48 + mt * 16 + gid;
                af[mt][0] = As[row * 20 + kk + tid4];
                af[mt][1] = As[(row + 8) * 20 + kk + tid4];
                af[mt][2] = As[row * 20 + kk + tid4 + 4];
                af[mt][3] = As[(row + 8) * 20 + kk + tid4 + 4];
            }
#pragma unroll
            for (int nt = 0; nt < 8; nt++) {
                const int col = wn * 64 + nt * 8 + gid;
                bf[nt][0] = Bs[(kk + tid4) * 200 + col];
                bf[nt][1] = Bs[(kk + tid4 + 4) * 200 + col];
            }
#pragma unroll
            for (int mt = 0; mt < 3; mt++)
#pragma unroll
                for (int nt = 0; nt < 8; nt++)
                    mma_tf32(acc[mt][nt], af[mt], bf[nt]);
        }
        __syncthreads();
    }

    if (isZ) {
        float* zb = g_Z + (size_t)b * CH * NVOX;
#pragma unroll
        for (int mt = 0; mt < 3; mt++) {
            const int r0 = wm * 48 + mt * 16 + gid;
#pragma unroll
            for (int nt = 0; nt < 8; nt++) {
                const int col = n0 + wn * 64 + nt * 8 + 2 * tid4;
                *(float2*)(zb + (size_t)r0 * NVOX + col) = make_float2(acc[mt][nt][0], acc[mt][nt][1]);
                *(float2*)(zb + (size_t)(r0 + 8) * NVOX + col) = make_float2(acc[mt][nt][2], acc[mt][nt][3]);
            }
        }
    } else {
        float* vb = g_V + (size_t)b * NVOX * CH;
#pragma unroll
        for (int mt = 0; mt < 3; mt++) {
            const int r0 = m0 + wm * 48 + mt * 16 + gid;
            const float b0 = beta[r0], b1 = beta[r0 + 8];
#pragma unroll
            for (int nt = 0; nt < 8; nt++) {
                const int pc = e * 192 + wn * 64 + nt * 8 + 2 * tid4;
                *(float2*)(vb + (size_t)r0 * 4608 + pc) =
                    make_float2(acc[mt][nt][0] + b0, acc[mt][nt][1] + b0);
                *(float2*)(vb + (size_t)(r0 + 8) * 4608 + pc) =
                    make_float2(acc[mt][nt][2] + b1, acc[mt][nt][3] + b1);
            }
        }
    }
}

// ---------------------------------------------------------------------------
// K3: score partials, float4 loads, double-buffered e-loop.
// ---------------------------------------------------------------------------
__global__ __launch_bounds__(256) void scores_kernel(const float* __restrict__ x)
{
    __shared__ float Xq[2][32][36], Zq[2][32][36], Xk[2][32][36], Zk[2][32][36];
    __shared__ float wbs[32];

    const int isl = blockIdx.x, h = blockIdx.y, b = blockIdx.z;
    const int i0  = isl * 32;
    const int t   = threadIdx.x;
    const int h32 = h * 32;

    const float* xb = x + (size_t)b * CH * NVOX;
    const float* zb = g_Z + (size_t)b * CH * NVOX;

    if (t < 32) wbs[t] = g_wb[i0 + t];

    const int li  = t >> 3;
    const int lc4 = (t & 7) << 2;
    const int cc  = t >> 3;
    const int d0  = (t & 7) << 2;

    float s[4] = {0.f, 0.f, 0.f, 0.f};
    float dac = 0.f, wac = 0.f;

    const size_t rowoff = (size_t)(i0 + li) * NVOX;
    float4 rq, rzq, rk, rzk;
    {
        const int u = h32 + lc4;
        rq  = *(const float4*)(xb + rowoff + u);
        rzq = *(const float4*)(zb + rowoff + u);
        rk  = *(const float4*)(xb + rowoff + u + 192);
        rzk = *(const float4*)(zb + rowoff + u + 192);
    }
    *(float4*)&Xq[0][li][lc4] = rq;  *(float4*)&Zq[0][li][lc4] = rzq;
    *(float4*)&Xk[0][li][lc4] = rk;  *(float4*)&Zk[0][li][lc4] = rzk;
    __syncthreads();

    for (int e = 0; e < 24; e++) {
        const int cur = e & 1, nxt = cur ^ 1;
        if (e < 23) {
            const int u = 576 * (e + 1) + h32 + lc4;
            rq  = *(const float4*)(xb + rowoff + u);
            rzq = *(const float4*)(zb + rowoff + u);
            rk  = *(const float4*)(xb + rowoff + u + 192);
            rzk = *(const float4*)(zb + rowoff + u + 192);
        }
#pragma unroll
        for (int i = 0; i < 32; i++) {
            const float qv = Xq[cur][i][cc];
            const float4 zv = *(const float4*)&Zk[cur][i][d0];
            s[0] += qv * zv.x; s[1] += qv * zv.y; s[2] += qv * zv.z; s[3] += qv * zv.w;
        }
        if (t < 32) {
#pragma unroll
            for (int i = 0; i < 32; i++) {
                const float xv = Xq[cur][i][t];
                dac += xv * Zq[cur][i][t];
                wac += wbs[i] * xv;
            }
        } else if (t < 64) {
            const int c = t - 32;
#pragma unroll
            for (int i = 0; i < 32; i++) {
                const float xv = Xk[cur][i][c];
                dac += xv * Zk[cur][i][c];
                wac += wbs[i] * xv;
            }
        }
        if (e < 23) {
            *(float4*)&Xq[nxt][li][lc4] = rq;  *(float4*)&Zq[nxt][li][lc4] = rzq;
            *(float4*)&Xk[nxt][li][lc4] = rk;  *(float4*)&Zk[nxt][li][lc4] = rzk;
        }
        __syncthreads();
    }

    float* sp = g_spart + (size_t)((b * HEADS + h) * 6 + isl) * 1152;
    sp[cc * 32 + d0 + 0] = s[0];
    sp[cc * 32 + d0 + 1] = s[1];
    sp[cc * 32 + d0 + 2] = s[2];
    sp[cc * 32 + d0 + 3] = s[3];
    if (t < 32)       { sp[1024 + t] = dac; sp[1088 + t] = wac; }
    else if (t < 64)  { sp[1056 + (t - 32)] = dac; sp[1120 + (t - 32)] = wac; }
}

// ---------------------------------------------------------------------------
// K4: reduce partials, assemble S + bias terms, normalize, softmax -> attn
// ---------------------------------------------------------------------------
__global__ __launch_bounds__(256) void softmax_kernel(const float* __restrict__ temp)
{
    __shared__ float sS[1024];
    __shared__ float snq[32], snk[32], swq[32], swk[32];

    const int h = blockIdx.x, b = blockIdx.y;
    const int t = threadIdx.x;
    const float b2 = g_c[0];
    const float* sp = g_spart + (size_t)((b * HEADS + h) * 6) * 1152;

#pragma unroll
    for (int i = 0; i < 4; i++) {
        const int e = t + i * 256;
        float a = 0.f;
        for (int s = 0; s < 6; s++) a += sp[s * 1152 + e];
        sS[e] = a;
    }
    if (t < 64) {
        float d = 0.f, wv = 0.f;
        const int od = 1024 + t, ow = 1088 + t;
        for (int s = 0; s < 6; s++) { d += sp[s * 1152 + od]; wv += sp[s * 1152 + ow]; }
        const float n2 = d + 2.f * wv + 24.f * b2;
        const float r = fmaxf(sqrtf(fmaxf(n2, 0.f)), EPSN);
        if (t < 32) { snq[t] = r; swq[t] = wv; }
        else        { snk[t - 32] = r; swk[t - 32] = wv; }
    }
    __syncthreads();

    const int w = t >> 5, lane = t & 31;
    const float tv = temp[h];
    float* ab = g_attn + (size_t)((b * HEADS + h) * HD) * HD;

    for (int r = 0; r < 4; r++) {
        const int c = w * 4 + r;
        const float Sfull = sS[c * 32 + lane] + swq[c] + swk[lane] + 24.f * b2;
        float L = Sfull / (snq[c] * snk[lane]) * tv;
        float mx = L;
#pragma unroll
        for (int o = 16; o > 0; o >>= 1) mx = fmaxf(mx, __shfl_xor_sync(0xffffffffu, mx, o));
        const float ev = expf(L - mx);
        float sm = ev;
#pragma unroll
        for (int o = 16; o > 0; o >>= 1) sm += __shfl_xor_sync(0xffffffffu, sm, o);
        ab[c * 32 + lane] = ev / sm;
    }
}

// ---------------------------------------------------------------------------
// K5: M[b][o][h*32+d] = sum_cc pwT[cc*6+h][o] * attn[b,h,cc,d]
// ---------------------------------------------------------------------------
__global__ __launch_bounds__(192) void mmix_kernel()
{
    __shared__ float att[32][33];
    const int h = blockIdx.x, b = blockIdx.y;
    const int t = threadIdx.x;

    const float* ab = g_attn + (size_t)((b * HEADS + h) * HD) * HD;
    for (int e = t; e < 1024; e += 192) att[e >> 5][e & 31] = ab[e];
    __syncthreads();

    float pwr[32];
#pragma unroll
    for (int cc = 0; cc < 32; cc++) pwr[cc] = g_pwT[(cc * HEADS + h) * CH + t];

    float* Mb = g_M + (size_t)b * CH * CH + t * CH + h * HD;
#pragma unroll 4
    for (int d = 0; d < 32; d++) {
        float s = 0.f;
#pragma unroll
        for (int cc = 0; cc < 32; cc++) s += pwr[cc] * att[cc][d];
        Mb[d] = s;
    }
}

// ---------------------------------------------------------------------------
// K6: y[b] = M[b] @ Vbuf[b]^T + proj_b.  BM=192, BN=192, 384 thr, warp 48x64.
// A,B double-buffered in dynamic smem, one barrier per k-iter.
// ---------------------------------------------------------------------------
__global__ __launch_bounds__(384, 1) void out_gemm(float* __restrict__ y,
                                                   const float* __restrict__ pbias)
{
    extern __shared__ unsigned smw[];
    unsigned* AS = smw;               // stage s at s*3840
    unsigned* BS = smw + 7680;        // stage s at s*3840 (192*20, n-major)

    const int b  = blockIdx.z;
    const int n0 = blockIdx.x * 192;
    const int t  = threadIdx.x;
    const int wid = t >> 5, lane = t & 31;
    const int wm = wid & 3, wn = wid >> 2;
    const int gid = lane >> 2, tid4 = lane & 3;

    const float* Mb = g_M + (size_t)b * CH * CH;
    const float* vb = g_V + (size_t)b * NVOX * CH;
    float* yb = y + (size_t)b * CH * NVOX;

    float acc[3][8][4];
#pragma unroll
    for (int i = 0; i < 3; i++)
#pragma unroll
        for (int j = 0; j < 8; j++)
#pragma unroll
            for (int e = 0; e < 4; e++) acc[i][j][e] = 0.f;

    const int arow0 = t >> 2, akq = (t & 3) * 4;

    float4 ar0, ar1, br0, br1;
#define LDAB_O(K0) { ar0 = *(const float4*)(Mb + (size_t)arow0 * CH + (K0) + akq);             \
                     ar1 = *(const float4*)(Mb + (size_t)(arow0 + 96) * CH + (K0) + akq);      \
                     br0 = *(const float4*)(vb + (size_t)(n0 + arow0) * CH + (K0) + akq);      \
                     br1 = *(const float4*)(vb + (size_t)(n0 + 96 + arow0) * CH + (K0) + akq); }
#define STAB_O(ST) { unsigned* a0 = AS + (ST) * 3840 + arow0 * 20 + akq;                        \
                     a0[0]=f2tf(ar0.x); a0[1]=f2tf(ar0.y); a0[2]=f2tf(ar0.z); a0[3]=f2tf(ar0.w);\
                     unsigned* a1 = AS + (ST) * 3840 + (arow0 + 96) * 20 + akq;                 \
                     a1[0]=f2tf(ar1.x); a1[1]=f2tf(ar1.y); a1[2]=f2tf(ar1.z); a1[3]=f2tf(ar1.w);\
                     unsigned* b0 = BS + (ST) * 3840 + arow0 * 20 + akq;                        \
                     b0[0]=f2tf(br0.x); b0[1]=f2tf(br0.y); b0[2]=f2tf(br0.z); b0[3]=f2tf(br0.w);\
                     unsigned* b1 = BS + (ST) * 3840 + (arow0 + 96) * 20 + akq;                 \
                     b1[0]=f2tf(br1.x); b1[1]=f2tf(br1.y); b1[2]=f2tf(br1.z); b1[3]=f2tf(br1.w); }

    LDAB_O(0);
    STAB_O(0);
    LDAB_O(16);
    __syncthreads();

    for (int it = 0; it < 12; it++) {
        const int st = it & 1;
        if (it < 11) { STAB_O(st ^ 1); }
        if (it < 10) { LDAB_O(16 * (it + 2)); }

        const unsigned* As = AS + st * 3840;
        const unsigned* Bs = BS + st * 3840;
#pragma unroll
        for (int h = 0; h < 2; h++) {
            const int kk = h * 8;
            unsigned af[3][4], bf[8][2];
#pragma unroll
            for (int mt = 0; mt < 3; mt++) {
                const int row = wm * 48 + mt * 16 + gid;
                af[mt][0] = As[row * 20 + kk + tid4];
                af[mt][1] = As[(row + 8) * 20 + kk + tid4];
                af[mt][2] = As[row * 20 + kk + tid4 + 4];
                af[mt][3] = As[(row + 8) * 20 + kk + tid4 + 4];
            }
#pragma unroll
            for (int nt = 0; nt < 8; nt++) {
                const int col = wn * 64 + nt * 8 + gid;
                bf[nt][0] = Bs[col * 20 + kk + tid4];
                bf[nt][1] = Bs[col * 20 + kk + tid4 + 4];
            }
#pragma unroll
            for (int mt = 0; mt < 3; mt++)
#pragma unroll
                for (int nt = 0; nt < 8; nt++)
                    mma_tf32(acc[mt][nt], af[mt], bf[nt]);
        }
        __syncthreads();
    }

#pragma unroll
    for (int mt = 0; mt < 3; mt++) {
        const int r0 = wm * 48 + mt * 16 + gid;
        const float b0 = pbias[r0], b1 = pbias[r0 + 8];
#pragma unroll
        for (int nt = 0; nt < 8; nt++) {
            const int col = n0 + wn * 64 + nt * 8 + 2 * tid4;
            *(float2*)(yb + (size_t)r0 * NVOX + col) =
                make_float2(acc[mt][nt][0] + b0, acc[mt][nt][1] + b0);
            *(float2*)(yb + (size_t)(r0 + 8) * NVOX + col) =
                make_float2(acc[mt][nt][2] + b1, acc[mt][nt][3] + b1);
        }
    }
}

// ---------------------------------------------------------------------------
extern "C" void kernel_launch(void* const* d_in, const int* in_sizes, int n_in,
                              void* d_out, int out_size)
{
    const float* x      = (const float*)d_in[0];
    const float* qkv_w  = (const float*)d_in[1];
    const float* qkv_b  = (const float*)d_in[2];
    const float* temp   = (const float*)d_in[3];
    const float* proj_w = (const float*)d_in[4];
    const float* proj_b = (const float*)d_in[5];
    float* y = (float*)d_out;

    // opt-in to >48KB dynamic smem (idempotent, capture-safe, no allocation)
    cudaFuncSetAttribute(zv_gemm,  cudaFuncAttributeMaxDynamicSharedMemorySize, 56320);
    cudaFuncSetAttribute(out_gemm, cudaFuncAttributeMaxDynamicSharedMemorySize, 61440);

    gw_kernel     <<<dim3(6, 6), 256>>>(qkv_w);
    wb_kernel     <<<1, 256>>>(qkv_w, qkv_b);
    ptrans_kernel <<<dim3(6, 6), 256>>>(proj_w);

    zv_gemm       <<<960, 384, 56320>>>(x, qkv_w, qkv_b);
    scores_kernel <<<dim3(6, HEADS, BATCH), 256>>>(x);
    softmax_kernel<<<dim3(HEADS, BATCH), 256>>>(temp);
    mmix_kernel   <<<dim3(HEADS, BATCH), 192>>>();
    out_gemm      <<<dim3(72, 1, BATCH), 384, 61440>>>(y, proj_b);
}

// round 8
// speedup vs baseline: 1.0883x; 1.0296x over previous
#include <cuda_runtime.h>
#include <math.h>

#define BATCH  8
#define CH     192
#define C3     576
#define NVOX   13824       // 24*24*24
#define HEADS  6
#define HD     32
#define EPSN   1e-12f

// Scratch
__device__ float g_Z[(size_t)BATCH * CH * NVOX];     // Z = Gw @ X (only q/k cols valid)
__device__ float g_V[(size_t)BATCH * NVOX * CH];     // Vbuf
__device__ float g_Gw[CH * CH];
__device__ float g_wb[CH];
__device__ float g_pwT[CH * CH];
__device__ float g_c[4];                             // [0] = b2
__device__ float g_spart[BATCH * HEADS * 6 * 1152];
__device__ float g_attn[BATCH * HEADS * HD * HD];
__device__ float g_M[BATCH * CH * CH];

// ---------------------------------------------------------------------------
__device__ __forceinline__ unsigned f2tf(float f) {
    unsigned u;
    asm("cvt.rna.tf32.f32 %0, %1;" : "=r"(u) : "f"(f));
    return u;
}
__device__ __forceinline__ void mma_tf32(float* c, const unsigned* a, const unsigned* b) {
    asm volatile(
        "mma.sync.aligned.m16n8k8.row.col.f32.tf32.tf32.f32 "
        "{%0,%1,%2,%3},{%4,%5,%6,%7},{%8,%9},{%0,%1,%2,%3};"
        : "+f"(c[0]), "+f"(c[1]), "+f"(c[2]), "+f"(c[3])
        : "r"(a[0]), "r"(a[1]), "r"(a[2]), "r"(a[3]), "r"(b[0]), "r"(b[1]));
}

// ---------------------------------------------------------------------------
// K0a: Gw = W^T W
// ---------------------------------------------------------------------------
__global__ __launch_bounds__(256) void gw_kernel(const float* __restrict__ w)
{
    __shared__ float Wi[32][33];
    __shared__ float Wj[32][33];
    const int i0 = blockIdx.x * 32, j0 = blockIdx.y * 32;
    const int t = threadIdx.x;
    const int ti = t & 31, tj = (t >> 5) * 4;
    float acc[4] = {0.f, 0.f, 0.f, 0.f};

    for (int a0 = 0; a0 < C3; a0 += 32) {
        __syncthreads();
#pragma unroll
        for (int l = 0; l < 4; l++) {
            const int a = (t >> 5) + 8 * l, c = t & 31;
            Wi[a][c] = w[(a0 + a) * CH + i0 + c];
            Wj[a][c] = w[(a0 + a) * CH + j0 + c];
        }
        __syncthreads();
#pragma unroll
        for (int a = 0; a < 32; a++) {
            const float wi = Wi[a][ti];
#pragma unroll
            for (int r = 0; r < 4; r++) acc[r] += wi * Wj[a][tj + r];
        }
    }
#pragma unroll
    for (int r = 0; r < 4; r++) g_Gw[(i0 + ti) * CH + j0 + tj + r] = acc[r];
}

// K0b: wb = W^T beta; b2 = sum beta^2.
__global__ __launch_bounds__(256) void wb_kernel(const float* __restrict__ w,
                                                 const float* __restrict__ beta)
{
    __shared__ float red[64];
    const int t = threadIdx.x;
    if (t < CH) {
        float s = 0.f;
        for (int a = 0; a < C3; a++) s += beta[a] * w[a * CH + t];
        g_wb[t] = s;
    }
    if (t < 64) {
        float p = 0.f;
        for (int a = t; a < C3; a += 64) p += beta[a] * beta[a];
        red[t] = p;
    }
    __syncthreads();
    if (t == 0) {
        float s = 0.f;
        for (int i = 0; i < 64; i++) s += red[i];
        g_c[0] = s;
    }
}

// K0c: pwT[c][o] = proj_w[o][c]
__global__ __launch_bounds__(256) void ptrans_kernel(const float* __restrict__ pw)
{
    __shared__ float tile[32][33];
    const int bx = blockIdx.x * 32, by = blockIdx.y * 32;
    const int tx = threadIdx.x & 31, ty = threadIdx.x >> 5;
#pragma unroll
    for (int l = 0; l < 4; l++)
        tile[ty + 8 * l][tx] = pw[(by + ty + 8 * l) * CH + bx + tx];
    __syncthreads();
#pragma unroll
    for (int l = 0; l < 4; l++)
        g_pwT[(bx + ty + 8 * l) * CH + by + tx] = tile[tx][ty + 8 * l];
}

// ---------------------------------------------------------------------------
// K1: Z[b] = Gw @ X[b], columns 576e + 96j, j<4.
// BM=192, BN=96, BK=16, 256 thr, 8 warps (4m x 2n), warp 48x48 (3x6).
// 2 CTAs/SM. A,B double-buffered static smem.
// ---------------------------------------------------------------------------
__global__ __launch_bounds__(256, 2) void z_gemm(const float* __restrict__ x)
{
    __shared__ unsigned As[2][192 * 20];
    __shared__ unsigned Bs[2][16 * 104];

    const int b = blockIdx.z;
    const int e = blockIdx.x >> 2, j = blockIdx.x & 3;
    const int n0 = 576 * e + 96 * j;
    const int t = threadIdx.x;
    const int wid = t >> 5, lane = t & 31;
    const int wm = wid & 3, wn = wid >> 2;
    const int gid = lane >> 2, tid4 = lane & 3;

    const float* bsrc = x + (size_t)b * CH * NVOX + n0;
    float* zb = g_Z + (size_t)b * CH * NVOX + n0;

    float acc[3][6][4];
#pragma unroll
    for (int i = 0; i < 3; i++)
#pragma unroll
        for (int q = 0; q < 6; q++)
#pragma unroll
            for (int r = 0; r < 4; r++) acc[i][q][r] = 0.f;

    float4 ar[3], br[2];
#define LDA_Z(K0) { _Pragma("unroll") for (int l = 0; l < 3; l++) {                      \
                      const int idx = l * 256 + t;                                       \
                      ar[l] = *(const float4*)(g_Gw + (idx >> 2) * CH + (K0) + (idx & 3) * 4); } }
#define LDB_Z(K0) { _Pragma("unroll") for (int l = 0; l < 2; l++) {                      \
                      const int idx = l * 256 + t;                                       \
                      if (idx < 384)                                                     \
                        br[l] = *(const float4*)(bsrc + (size_t)((K0) + idx / 24) * NVOX + (idx % 24) * 4); } }
#define STA_G(ST) { _Pragma("unroll") for (int l = 0; l < 3; l++) {                      \
                      const int idx = l * 256 + t;                                       \
                      unsigned* d = &As[ST][(idx >> 2) * 20 + (idx & 3) * 4];            \
                      d[0]=f2tf(ar[l].x); d[1]=f2tf(ar[l].y); d[2]=f2tf(ar[l].z); d[3]=f2tf(ar[l].w); } }
#define STB_G(ST) { _Pragma("unroll") for (int l = 0; l < 2; l++) {                      \
                      const int idx = l * 256 + t;                                       \
                      if (idx < 384) {                                                   \
                        unsigned* d = &Bs[ST][(idx / 24) * 104 + (idx % 24) * 4];        \
                        d[0]=f2tf(br[l].x); d[1]=f2tf(br[l].y); d[2]=f2tf(br[l].z); d[3]=f2tf(br[l].w); } } }

    LDA_Z(0); LDB_Z(0);
    STA_G(0); STB_G(0);
    LDA_Z(16); LDB_Z(16);
    __syncthreads();

    for (int it = 0; it < 12; it++) {
        const int st = it & 1;
        if (it < 11) { STA_G(st ^ 1); STB_G(st ^ 1); }
        if (it < 10) { LDA_Z(16 * (it + 2)); LDB_Z(16 * (it + 2)); }

        const unsigned* Asl = As[st];
        const unsigned* Bsl = Bs[st];
#pragma unroll
        for (int h = 0; h < 2; h++) {
            const int kk = h * 8;
            unsigned af[3][4], bf[6][2];
#pragma unroll
            for (int mt = 0; mt < 3; mt++) {
                const int row = wm * 48 + mt * 16 + gid;
                af[mt][0] = Asl[row * 20 + kk + tid4];
                af[mt][1] = Asl[(row + 8) * 20 + kk + tid4];
                af[mt][2] = Asl[row * 20 + kk + tid4 + 4];
                af[mt][3] = Asl[(row + 8) * 20 + kk + tid4 + 4];
            }
#pragma unroll
            for (int nt = 0; nt < 6; nt++) {
                const int col = wn * 48 + nt * 8 + gid;
                bf[nt][0] = Bsl[(kk + tid4) * 104 + col];
                bf[nt][1] = Bsl[(kk + tid4 + 4) * 104 + col];
            }
#pragma unroll
            for (int mt = 0; mt < 3; mt++)
#pragma unroll
                for (int nt = 0; nt < 6; nt++)
                    mma_tf32(acc[mt][nt], af[mt], bf[nt]);
        }
        __syncthreads();
    }

#pragma unroll
    for (int mt = 0; mt < 3; mt++) {
        const int r0 = wm * 48 + mt * 16 + gid;
#pragma unroll
        for (int nt = 0; nt < 6; nt++) {
            const int col = wn * 48 + nt * 8 + 2 * tid4;
            *(float2*)(zb + (size_t)r0 * NVOX + col) = make_float2(acc[mt][nt][0], acc[mt][nt][1]);
            *(float2*)(zb + (size_t)(r0 + 8) * NVOX + col) = make_float2(acc[mt][nt][2], acc[mt][nt][3]);
        }
    }
}

// ---------------------------------------------------------------------------
// K2: Vbuf = W[m0:m0+192] @ Xv(e, 96j) + beta.  Same tiling as K1.
// ---------------------------------------------------------------------------
__global__ __launch_bounds__(256, 2) void v_gemm(const float* __restrict__ x,
                                                 const float* __restrict__ qkv_w,
                                                 const float* __restrict__ beta)
{
    __shared__ unsigned As[2][192 * 20];
    __shared__ unsigned Bs[2][16 * 104];

    const int b = blockIdx.z;
    const int e = blockIdx.x >> 1, j = blockIdx.x & 1;
    const int m0 = blockIdx.y * 192;
    const int t = threadIdx.x;
    const int wid = t >> 5, lane = t & 31;
    const int wm = wid & 3, wn = wid >> 2;
    const int gid = lane >> 2, tid4 = lane & 3;

    const float* bsrc = x + (size_t)b * CH * NVOX + 576 * e + 384 + 96 * j;
    const float* Asrc = qkv_w + (size_t)m0 * CH;
    float* vb = g_V + (size_t)b * NVOX * CH;

    float acc[3][6][4];
#pragma unroll
    for (int i = 0; i < 3; i++)
#pragma unroll
        for (int q = 0; q < 6; q++)
#pragma unroll
            for (int r = 0; r < 4; r++) acc[i][q][r] = 0.f;

    float4 ar[3], br[2];
#define LDA_V(K0) { _Pragma("unroll") for (int l = 0; l < 3; l++) {                      \
                      const int idx = l * 256 + t;                                       \
                      ar[l] = *(const float4*)(Asrc + (size_t)(idx >> 2) * CH + (K0) + (idx & 3) * 4); } }

    LDA_V(0); LDB_Z(0);
    STA_G(0); STB_G(0);
    LDA_V(16); LDB_Z(16);
    __syncthreads();

    for (int it = 0; it < 12; it++) {
        const int st = it & 1;
        if (it < 11) { STA_G(st ^ 1); STB_G(st ^ 1); }
        if (it < 10) { LDA_V(16 * (it + 2)); LDB_Z(16 * (it + 2)); }

        const unsigned* Asl = As[st];
        const unsigned* Bsl = Bs[st];
#pragma unroll
        for (int h = 0; h < 2; h++) {
            const int kk = h * 8;
            unsigned af[3][4], bf[6][2];
#pragma unroll
            for (int mt = 0; mt < 3; mt++) {
                const int row = wm * 48 + mt * 16 + gid;
                af[mt][0] = Asl[row * 20 + kk + tid4];
                af[mt][1] = Asl[(row + 8) * 20 + kk + tid4];
                af[mt][2] = Asl[row * 20 + kk + tid4 + 4];
                af[mt][3] = Asl[(row + 8) * 20 + kk + tid4 + 4];
            }
#pragma unroll
            for (int nt = 0; nt < 6; nt++) {
                const int col = wn * 48 + nt * 8 + gid;
                bf[nt][0] = Bsl[(kk + tid4) * 104 + col];
                bf[nt][1] = Bsl[(kk + tid4 + 4) * 104 + col];
            }
#pragma unroll
            for (int mt = 0; mt < 3; mt++)
#pragma unroll
                for (int nt = 0; nt < 6; nt++)
                    mma_tf32(acc[mt][nt], af[mt], bf[nt]);
        }
        __syncthreads();
    }

#pragma unroll
    for (int mt = 0; mt < 3; mt++) {
        const int r0 = m0 + wm * 48 + mt * 16 + gid;
        const float b0 = beta[r0], b1 = beta[r0 + 8];
#pragma unroll
        for (int nt = 0; nt < 6; nt++) {
            const int pc = e * 192 + 96 * j + wn * 48 + nt * 8 + 2 * tid4;
            *(float2*)(vb + (size_t)r0 * 4608 + pc) =
                make_float2(acc[mt][nt][0] + b0, acc[mt][nt][1] + b0);
            *(float2*)(vb + (size_t)(r0 + 8) * 4608 + pc) =
                make_float2(acc[mt][nt][2] + b1, acc[mt][nt][3] + b1);
        }
    }
}

// ---------------------------------------------------------------------------
// K3: score partials, float4 loads, double-buffered e-loop.
// ---------------------------------------------------------------------------
__global__ __launch_bounds__(256) void scores_kernel(const float* __restrict__ x)
{
    __shared__ float Xq[2][32][36], Zq[2][32][36], Xk[2][32][36], Zk[2][32][36];
    __shared__ float wbs[32];

    const int isl = blockIdx.x, h = blockIdx.y, b = blockIdx.z;
    const int i0  = isl * 32;
    const int t   = threadIdx.x;
    const int h32 = h * 32;

    const float* xb = x + (size_t)b * CH * NVOX;
    const float* zb = g_Z + (size_t)b * CH * NVOX;

    if (t < 32) wbs[t] = g_wb[i0 + t];

    const int li  = t >> 3;
    const int lc4 = (t & 7) << 2;
    const int cc  = t >> 3;
    const int d0  = (t & 7) << 2;

    float s[4] = {0.f, 0.f, 0.f, 0.f};
    float dac = 0.f, wac = 0.f;

    const size_t rowoff = (size_t)(i0 + li) * NVOX;
    float4 rq, rzq, rk, rzk;
    {
        const int u = h32 + lc4;
        rq  = *(const float4*)(xb + rowoff + u);
        rzq = *(const float4*)(zb + rowoff + u);
        rk  = *(const float4*)(xb + rowoff + u + 192);
        rzk = *(const float4*)(zb + rowoff + u + 192);
    }
    *(float4*)&Xq[0][li][lc4] = rq;  *(float4*)&Zq[0][li][lc4] = rzq;
    *(float4*)&Xk[0][li][lc4] = rk;  *(float4*)&Zk[0][li][lc4] = rzk;
    __syncthreads();

    for (int e = 0; e < 24; e++) {
        const int cur = e & 1, nxt = cur ^ 1;
        if (e < 23) {
            const int u = 576 * (e + 1) + h32 + lc4;
            rq  = *(const float4*)(xb + rowoff + u);
            rzq = *(const float4*)(zb + rowoff + u);
            rk  = *(const float4*)(xb + rowoff + u + 192);
            rzk = *(const float4*)(zb + rowoff + u + 192);
        }
#pragma unroll
        for (int i = 0; i < 32; i++) {
            const float qv = Xq[cur][i][cc];
            const float4 zv = *(const float4*)&Zk[cur][i][d0];
            s[0] += qv * zv.x; s[1] += qv * zv.y; s[2] += qv * zv.z; s[3] += qv * zv.w;
        }
        if (t < 32) {
#pragma unroll
            for (int i = 0; i < 32; i++) {
                const float xv = Xq[cur][i][t];
                dac += xv * Zq[cur][i][t];
                wac += wbs[i] * xv;
            }
        } else if (t < 64) {
            const int c = t - 32;
#pragma unroll
            for (int i = 0; i < 32; i++) {
                const float xv = Xk[cur][i][c];
                dac += xv * Zk[cur][i][c];
                wac += wbs[i] * xv;
            }
        }
        if (e < 23) {
            *(float4*)&Xq[nxt][li][lc4] = rq;  *(float4*)&Zq[nxt][li][lc4] = rzq;
            *(float4*)&Xk[nxt][li][lc4] = rk;  *(float4*)&Zk[nxt][li][lc4] = rzk;
        }
        __syncthreads();
    }

    float* sp = g_spart + (size_t)((b * HEADS + h) * 6 + isl) * 1152;
    sp[cc * 32 + d0 + 0] = s[0];
    sp[cc * 32 + d0 + 1] = s[1];
    sp[cc * 32 + d0 + 2] = s[2];
    sp[cc * 32 + d0 + 3] = s[3];
    if (t < 32)       { sp[1024 + t] = dac; sp[1088 + t] = wac; }
    else if (t < 64)  { sp[1056 + (t - 32)] = dac; sp[1120 + (t - 32)] = wac; }
}

// ---------------------------------------------------------------------------
// K4: reduce partials, assemble S + bias terms, normalize, softmax -> attn
// ---------------------------------------------------------------------------
__global__ __launch_bounds__(256) void softmax_kernel(const float* __restrict__ temp)
{
    __shared__ float sS[1024];
    __shared__ float snq[32], snk[32], swq[32], swk[32];

    const int h = blockIdx.x, b = blockIdx.y;
    const int t = threadIdx.x;
    const float b2 = g_c[0];
    const float* sp = g_spart + (size_t)((b * HEADS + h) * 6) * 1152;

#pragma unroll
    for (int i = 0; i < 4; i++) {
        const int e = t + i * 256;
        float a = 0.f;
        for (int s = 0; s < 6; s++) a += sp[s * 1152 + e];
        sS[e] = a;
    }
    if (t < 64) {
        float d = 0.f, wv = 0.f;
        const int od = 1024 + t, ow = 1088 + t;
        for (int s = 0; s < 6; s++) { d += sp[s * 1152 + od]; wv += sp[s * 1152 + ow]; }
        const float n2 = d + 2.f * wv + 24.f * b2;
        const float r = fmaxf(sqrtf(fmaxf(n2, 0.f)), EPSN);
        if (t < 32) { snq[t] = r; swq[t] = wv; }
        else        { snk[t - 32] = r; swk[t - 32] = wv; }
    }
    __syncthreads();

    const int w = t >> 5, lane = t & 31;
    const float tv = temp[h];
    float* ab = g_attn + (size_t)((b * HEADS + h) * HD) * HD;

    for (int r = 0; r < 4; r++) {
        const int c = w * 4 + r;
        const float Sfull = sS[c * 32 + lane] + swq[c] + swk[lane] + 24.f * b2;
        float L = Sfull / (snq[c] * snk[lane]) * tv;
        float mx = L;
#pragma unroll
        for (int o = 16; o > 0; o >>= 1) mx = fmaxf(mx, __shfl_xor_sync(0xffffffffu, mx, o));
        const float ev = expf(L - mx);
        float sm = ev;
#pragma unroll
        for (int o = 16; o > 0; o >>= 1) sm += __shfl_xor_sync(0xffffffffu, sm, o);
        ab[c * 32 + lane] = ev / sm;
    }
}

// ---------------------------------------------------------------------------
// K5: M[b][o][h*32+d] = sum_cc pwT[cc*6+h][o] * attn[b,h,cc,d]
// ---------------------------------------------------------------------------
__global__ __launch_bounds__(192) void mmix_kernel()
{
    __shared__ float att[32][33];
    const int h = blockIdx.x, b = blockIdx.y;
    const int t = threadIdx.x;

    const float* ab = g_attn + (size_t)((b * HEADS + h) * HD) * HD;
    for (int e = t; e < 1024; e += 192) att[e >> 5][e & 31] = ab[e];
    __syncthreads();

    float pwr[32];
#pragma unroll
    for (int cc = 0; cc < 32; cc++) pwr[cc] = g_pwT[(cc * HEADS + h) * CH + t];

    float* Mb = g_M + (size_t)b * CH * CH + t * CH + h * HD;
#pragma unroll 4
    for (int d = 0; d < 32; d++) {
        float s = 0.f;
#pragma unroll
        for (int cc = 0; cc < 32; cc++) s += pwr[cc] * att[cc][d];
        Mb[d] = s;
    }
}

// ---------------------------------------------------------------------------
// K6: y[b] = M[b] @ Vbuf[b]^T + proj_b.  BM=192, BN=96, 256 thr, 2 CTA/SM.
// B n-major (Bs[n][20]).
// ---------------------------------------------------------------------------
__global__ __launch_bounds__(256, 2) void out_gemm(float* __restrict__ y,
                                                   const float* __restrict__ pbias)
{
    __shared__ unsigned As[2][192 * 20];
    __shared__ unsigned Bs[2][96 * 20];

    const int b  = blockIdx.z;
    const int n0 = blockIdx.x * 96;
    const int t  = threadIdx.x;
    const int wid = t >> 5, lane = t & 31;
    const int wm = wid & 3, wn = wid >> 2;
    const int gid = lane >> 2, tid4 = lane & 3;

    const float* Mb = g_M + (size_t)b * CH * CH;
    const float* vb = g_V + (size_t)b * NVOX * CH;
    float* yb = y + (size_t)b * CH * NVOX;

    float acc[3][6][4];
#pragma unroll
    for (int i = 0; i < 3; i++)
#pragma unroll
        for (int q = 0; q < 6; q++)
#pragma unroll
            for (int r = 0; r < 4; r++) acc[i][q][r] = 0.f;

    float4 ar[3], br[2];
#define LDA_O(K0) { _Pragma("unroll") for (int l = 0; l < 3; l++) {                      \
                      const int idx = l * 256 + t;                                       \
                      ar[l] = *(const float4*)(Mb + (size_t)(idx >> 2) * CH + (K0) + (idx & 3) * 4); } }
#define LDB_O(K0) { _Pragma("unroll") for (int l = 0; l < 2; l++) {                      \
                      const int idx = l * 256 + t;                                       \
                      if (idx < 384)                                                     \
                        br[l] = *(const float4*)(vb + (size_t)(n0 + (idx >> 2)) * CH + (K0) + (idx & 3) * 4); } }
#define STB_O(ST) { _Pragma("unroll") for (int l = 0; l < 2; l++) {                      \
                      const int idx = l * 256 + t;                                       \
                      if (idx < 384) {                                                   \
                        unsigned* d = &Bs[ST][(idx >> 2) * 20 + (idx & 3) * 4];          \
                        d[0]=f2tf(br[l].x); d[1]=f2tf(br[l].y); d[2]=f2tf(br[l].z); d[3]=f2tf(br[l].w); } } }

    LDA_O(0); LDB_O(0);
    STA_G(0); STB_O(0);
    LDA_O(16); LDB_O(16);
    __syncthreads();

    for (int it = 0; it < 12; it++) {
        const int st = it & 1;
        if (it < 11) { STA_G(st ^ 1); STB_O(st ^ 1); }
        if (it < 10) { LDA_O(16 * (it + 2)); LDB_O(16 * (it + 2)); }

        const unsigned* Asl = As[st];
        const unsigned* Bsl = Bs[st];
#pragma unroll
        for (int h = 0; h < 2; h++) {
            const int kk = h * 8;
            unsigned af[3][4], bf[6][2];
#pragma unroll
            for (int mt = 0; mt < 3; mt++) {
                const int row = wm * 48 + mt * 16 + gid;
                af[mt][0] = Asl[row * 20 + kk + tid4];
                af[mt][1] = Asl[(row + 8) * 20 + kk + tid4];
                af[mt][2] = Asl[row * 20 + kk + tid4 + 4];
                af[mt][3] = Asl[(row + 8) * 20 + kk + tid4 + 4];
            }
#pragma unroll
            for (int nt = 0; nt < 6; nt++) {
                const int col = wn * 48 + nt * 8 + gid;
                bf[nt][0] = Bsl[col * 20 + kk + tid4];
                bf[nt][1] = Bsl[col * 20 + kk + tid4 + 4];
            }
#pragma unroll
            for (int mt = 0; mt < 3; mt++)
#pragma unroll
                for (int nt = 0; nt < 6; nt++)
                    mma_tf32(acc[mt][nt], af[mt], bf[nt]);
        }
        __syncthreads();
    }

#pragma unroll
    for (int mt = 0; mt < 3; mt++) {
        const int r0 = wm * 48 + mt * 16 + gid;
        const float b0 = pbias[r0], b1 = pbias[r0 + 8];
#pragma unroll
        for (int nt = 0; nt < 6; nt++) {
            const int col = n0 + wn * 48 + nt * 8 + 2 * tid4;
            *(float2*)(yb + (size_t)r0 * NVOX + col) =
                make_float2(acc[mt][nt][0] + b0, acc[mt][nt][1] + b0);
            *(float2*)(yb + (size_t)(r0 + 8) * NVOX + col) =
                make_float2(acc[mt][nt][2] + b1, acc[mt][nt][3] + b1);
        }
    }
}

// ---------------------------------------------------------------------------
extern "C" void kernel_launch(void* const* d_in, const int* in_sizes, int n_in,
                              void* d_out, int out_size)
{
    const float* x      = (const float*)d_in[0];
    const float* qkv_w  = (const float*)d_in[1];
    const float* qkv_b  = (const float*)d_in[2];
    const float* temp   = (const float*)d_in[3];
    const float* proj_w = (const float*)d_in[4];
    const float* proj_b = (const float*)d_in[5];
    float* y = (float*)d_out;

    gw_kernel     <<<dim3(6, 6), 256>>>(qkv_w);
    wb_kernel     <<<1, 256>>>(qkv_w, qkv_b);
    ptrans_kernel <<<dim3(6, 6), 256>>>(proj_w);

    z_gemm        <<<dim3(96, 1, BATCH), 256>>>(x);
    v_gemm        <<<dim3(48, 3, BATCH), 256>>>(x, qkv_w, qkv_b);
    scores_kernel <<<dim3(6, HEADS, BATCH), 256>>>(x);
    softmax_kernel<<<dim3(HEADS, BATCH), 256>>>(temp);
    mmix_kernel   <<<dim3(HEADS, BATCH), 192>>>();
    out_gemm      <<<dim3(144, 1, BATCH), 256>>>(y, proj_b);
}

// round 10
// speedup vs baseline: 1.1279x; 1.0364x over previous
#include <cuda_runtime.h>
#include <math.h>

#define BATCH  8
#define CH     192
#define C3     576
#define NVOX   13824       // 24*24*24
#define HEADS  6
#define HD     32
#define EPSN   1e-12f

// Scratch
__device__ float g_Z[(size_t)BATCH * CH * NVOX];     // Z = Gw @ X (only q/k cols valid)
__device__ float g_V[(size_t)BATCH * NVOX * CH];     // Vbuf
__device__ float g_Gw[CH * CH];
__device__ float g_wb[CH];
__device__ float g_pwT[CH * CH];
__device__ float g_c[4];                             // [0] = b2
__device__ float g_spart[BATCH * HEADS * 12 * 1152];
__device__ float g_attn[BATCH * HEADS * HD * HD];
__device__ float g_M[BATCH * CH * CH];

// ---------------------------------------------------------------------------
__device__ __forceinline__ unsigned f2tf(float f) {
    unsigned u;
    asm("cvt.rna.tf32.f32 %0, %1;" : "=r"(u) : "f"(f));
    return u;
}
__device__ __forceinline__ void mma_tf32(float* c, const unsigned* a, const unsigned* b) {
    asm volatile(
        "mma.sync.aligned.m16n8k8.row.col.f32.tf32.tf32.f32 "
        "{%0,%1,%2,%3},{%4,%5,%6,%7},{%8,%9},{%0,%1,%2,%3};"
        : "+f"(c[0]), "+f"(c[1]), "+f"(c[2]), "+f"(c[3])
        : "r"(a[0]), "r"(a[1]), "r"(a[2]), "r"(a[3]), "r"(b[0]), "r"(b[1]));
}

// ---------------------------------------------------------------------------
// K0 merged prekernel: blocks 0..35 -> Gw = W^T W tiles;
//                      blocks 36..71 -> pwT transpose tiles;
//                      block  72     -> wb + b2.
// ---------------------------------------------------------------------------
__global__ __launch_bounds__(256) void pre_kernel(const float* __restrict__ w,
                                                  const float* __restrict__ beta,
                                                  const float* __restrict__ pw)
{
    __shared__ float sh[2112];   // 2 * 32 * 33
    const int bid = blockIdx.x;
    const int t = threadIdx.x;

    if (bid < 36) {
        float (*Wi)[33] = (float (*)[33])sh;
        float (*Wj)[33] = (float (*)[33])(sh + 1056);
        const int i0 = (bid % 6) * 32, j0 = (bid / 6) * 32;
        const int ti = t & 31, tj = (t >> 5) * 4;
        float acc[4] = {0.f, 0.f, 0.f, 0.f};
        for (int a0 = 0; a0 < C3; a0 += 32) {
            __syncthreads();
#pragma unroll
            for (int l = 0; l < 4; l++) {
                const int a = (t >> 5) + 8 * l, c = t & 31;
                Wi[a][c] = w[(a0 + a) * CH + i0 + c];
                Wj[a][c] = w[(a0 + a) * CH + j0 + c];
            }
            __syncthreads();
#pragma unroll
            for (int a = 0; a < 32; a++) {
                const float wi = Wi[a][ti];
#pragma unroll
                for (int r = 0; r < 4; r++) acc[r] += wi * Wj[a][tj + r];
            }
        }
#pragma unroll
        for (int r = 0; r < 4; r++) g_Gw[(i0 + ti) * CH + j0 + tj + r] = acc[r];
    } else if (bid < 72) {
        float (*tile)[33] = (float (*)[33])sh;
        const int bb = bid - 36;
        const int bx = (bb % 6) * 32, by = (bb / 6) * 32;
        const int tx = t & 31, ty = t >> 5;
#pragma unroll
        for (int l = 0; l < 4; l++)
            tile[ty + 8 * l][tx] = pw[(by + ty + 8 * l) * CH + bx + tx];
        __syncthreads();
#pragma unroll
        for (int l = 0; l < 4; l++)
            g_pwT[(bx + ty + 8 * l) * CH + by + tx] = tile[tx][ty + 8 * l];
    } else {
        if (t < CH) {
            float s = 0.f;
            for (int a = 0; a < C3; a++) s += beta[a] * w[a * CH + t];
            g_wb[t] = s;
        }
        if (t < 64) {
            float p = 0.f;
            for (int a = t; a < C3; a += 64) p += beta[a] * beta[a];
            sh[t] = p;
        }
        __syncthreads();
        if (t == 0) {
            float s = 0.f;
            for (int i = 0; i < 64; i++) s += sh[i];
            g_c[0] = s;
        }
    }
}

// ---------------------------------------------------------------------------
// K1: Z[b] = Gw @ X[b], columns 576e + 96j, j<4.
// BM=192, BN=96, BK=16, 256 thr, 8 warps (4m x 2n), warp 48x48. 2 CTA/SM.
// ---------------------------------------------------------------------------
__global__ __launch_bounds__(256, 2) void z_gemm(const float* __restrict__ x)
{
    __shared__ unsigned As[2][192 * 20];
    __shared__ unsigned Bs[2][16 * 104];

    const int b = blockIdx.z;
    const int e = blockIdx.x >> 2, j = blockIdx.x & 3;
    const int n0 = 576 * e + 96 * j;
    const int t = threadIdx.x;
    const int wid = t >> 5, lane = t & 31;
    const int wm = wid & 3, wn = wid >> 2;
    const int gid = lane >> 2, tid4 = lane & 3;

    const float* bsrc = x + (size_t)b * CH * NVOX + n0;
    float* zb = g_Z + (size_t)b * CH * NVOX + n0;

    float acc[3][6][4];
#pragma unroll
    for (int i = 0; i < 3; i++)
#pragma unroll
        for (int q = 0; q < 6; q++)
#pragma unroll
            for (int r = 0; r < 4; r++) acc[i][q][r] = 0.f;

    float4 ar[3], br[2];
#define LDA_Z(K0) { _Pragma("unroll") for (int l = 0; l < 3; l++) {                      \
                      const int idx = l * 256 + t;                                       \
                      ar[l] = *(const float4*)(g_Gw + (idx >> 2) * CH + (K0) + (idx & 3) * 4); } }
#define LDB_Z(K0) { _Pragma("unroll") for (int l = 0; l < 2; l++) {                      \
                      const int idx = l * 256 + t;                                       \
                      if (idx < 384)                                                     \
                        br[l] = *(const float4*)(bsrc + (size_t)((K0) + idx / 24) * NVOX + (idx % 24) * 4); } }
#define STA_G(ST) { _Pragma("unroll") for (int l = 0; l < 3; l++) {                      \
                      const int idx = l * 256 + t;                                       \
                      unsigned* d = &As[ST][(idx >> 2) * 20 + (idx & 3) * 4];            \
                      d[0]=f2tf(ar[l].x); d[1]=f2tf(ar[l].y); d[2]=f2tf(ar[l].z); d[3]=f2tf(ar[l].w); } }
#define STB_G(ST) { _Pragma("unroll") for (int l = 0; l < 2; l++) {                      \
                      const int idx = l * 256 + t;                                       \
                      if (idx < 384) {                                                   \
                        unsigned* d = &Bs[ST][(idx / 24) * 104 + (idx % 24) * 4];        \
                        d[0]=f2tf(br[l].x); d[1]=f2tf(br[l].y); d[2]=f2tf(br[l].z); d[3]=f2tf(br[l].w); } } }

    LDA_Z(0); LDB_Z(0);
    STA_G(0); STB_G(0);
    LDA_Z(16); LDB_Z(16);
    __syncthreads();

    for (int it = 0; it < 12; it++) {
        const int st = it & 1;
        if (it < 11) { STA_G(st ^ 1); STB_G(st ^ 1); }
        if (it < 10) { LDA_Z(16 * (it + 2)); LDB_Z(16 * (it + 2)); }

        const unsigned* Asl = As[st];
        const unsigned* Bsl = Bs[st];
#pragma unroll
        for (int h = 0; h < 2; h++) {
            const int kk = h * 8;
            unsigned af[3][4], bf[6][2];
#pragma unroll
            for (int mt = 0; mt < 3; mt++) {
                const int row = wm * 48 + mt * 16 + gid;
                af[mt][0] = Asl[row * 20 + kk + tid4];
                af[mt][1] = Asl[(row + 8) * 20 + kk + tid4];
                af[mt][2] = Asl[row * 20 + kk + tid4 + 4];
                af[mt][3] = Asl[(row + 8) * 20 + kk + tid4 + 4];
            }
#pragma unroll
            for (int nt = 0; nt < 6; nt++) {
                const int col = wn * 48 + nt * 8 + gid;
                bf[nt][0] = Bsl[(kk + tid4) * 104 + col];
                bf[nt][1] = Bsl[(kk + tid4 + 4) * 104 + col];
            }
#pragma unroll
            for (int mt = 0; mt < 3; mt++)
#pragma unroll
                for (int nt = 0; nt < 6; nt++)
                    mma_tf32(acc[mt][nt], af[mt], bf[nt]);
        }
        __syncthreads();
    }

#pragma unroll
    for (int mt = 0; mt < 3; mt++) {
        const int r0 = wm * 48 + mt * 16 + gid;
#pragma unroll
        for (int nt = 0; nt < 6; nt++) {
            const int col = wn * 48 + nt * 8 + 2 * tid4;
            *(float2*)(zb + (size_t)r0 * NVOX + col) = make_float2(acc[mt][nt][0], acc[mt][nt][1]);
            *(float2*)(zb + (size_t)(r0 + 8) * NVOX + col) = make_float2(acc[mt][nt][2], acc[mt][nt][3]);
        }
    }
}

// ---------------------------------------------------------------------------
// K2: Vbuf = W[m0:m0+192] @ Xv(e, 96j) + beta.  Same tiling as K1.
// ---------------------------------------------------------------------------
__global__ __launch_bounds__(256, 2) void v_gemm(const float* __restrict__ x,
                                                 const float* __restrict__ qkv_w,
                                                 const float* __restrict__ beta)
{
    __shared__ unsigned As[2][192 * 20];
    __shared__ unsigned Bs[2][16 * 104];

    const int b = blockIdx.z;
    const int e = blockIdx.x >> 1, j = blockIdx.x & 1;
    const int m0 = blockIdx.y * 192;
    const int t = threadIdx.x;
    const int wid = t >> 5, lane = t & 31;
    const int wm = wid & 3, wn = wid >> 2;
    const int gid = lane >> 2, tid4 = lane & 3;

    const float* bsrc = x + (size_t)b * CH * NVOX + 576 * e + 384 + 96 * j;
    const float* Asrc = qkv_w + (size_t)m0 * CH;
    float* vb = g_V + (size_t)b * NVOX * CH;

    float acc[3][6][4];
#pragma unroll
    for (int i = 0; i < 3; i++)
#pragma unroll
        for (int q = 0; q < 6; q++)
#pragma unroll
            for (int r = 0; r < 4; r++) acc[i][q][r] = 0.f;

    float4 ar[3], br[2];
#define LDA_V(K0) { _Pragma("unroll") for (int l = 0; l < 3; l++) {                      \
                      const int idx = l * 256 + t;                                       \
                      ar[l] = *(const float4*)(Asrc + (size_t)(idx >> 2) * CH + (K0) + (idx & 3) * 4); } }

    LDA_V(0); LDB_Z(0);
    STA_G(0); STB_G(0);
    LDA_V(16); LDB_Z(16);
    __syncthreads();

    for (int it = 0; it < 12; it++) {
        const int st = it & 1;
        if (it < 11) { STA_G(st ^ 1); STB_G(st ^ 1); }
        if (it < 10) { LDA_V(16 * (it + 2)); LDB_Z(16 * (it + 2)); }

        const unsigned* Asl = As[st];
        const unsigned* Bsl = Bs[st];
#pragma unroll
        for (int h = 0; h < 2; h++) {
            const int kk = h * 8;
            unsigned af[3][4], bf[6][2];
#pragma unroll
            for (int mt = 0; mt < 3; mt++) {
                const int row = wm * 48 + mt * 16 + gid;
                af[mt][0] = Asl[row * 20 + kk + tid4];
                af[mt][1] = Asl[(row + 8) * 20 + kk + tid4];
                af[mt][2] = Asl[row * 20 + kk + tid4 + 4];
                af[mt][3] = Asl[(row + 8) * 20 + kk + tid4 + 4];
            }
#pragma unroll
            for (int nt = 0; nt < 6; nt++) {
                const int col = wn * 48 + nt * 8 + gid;
                bf[nt][0] = Bsl[(kk + tid4) * 104 + col];
                bf[nt][1] = Bsl[(kk + tid4 + 4) * 104 + col];
            }
#pragma unroll
            for (int mt = 0; mt < 3; mt++)
#pragma unroll
                for (int nt = 0; nt < 6; nt++)
                    mma_tf32(acc[mt][nt], af[mt], bf[nt]);
        }
        __syncthreads();
    }

#pragma unroll
    for (int mt = 0; mt < 3; mt++) {
        const int r0 = m0 + wm * 48 + mt * 16 + gid;
        const float b0 = beta[r0], b1 = beta[r0 + 8];
#pragma unroll
        for (int nt = 0; nt < 6; nt++) {
            const int pc = e * 192 + 96 * j + wn * 48 + nt * 8 + 2 * tid4;
            *(float2*)(vb + (size_t)r0 * 4608 + pc) =
                make_float2(acc[mt][nt][0] + b0, acc[mt][nt][1] + b0);
            *(float2*)(vb + (size_t)(r0 + 8) * 4608 + pc) =
                make_float2(acc[mt][nt][2] + b1, acc[mt][nt][3] + b1);
        }
    }
}

// ---------------------------------------------------------------------------
// K3: score partials, split over (isl, e-half). grid (12, H, B).
// ---------------------------------------------------------------------------
__global__ __launch_bounds__(256) void scores_kernel(const float* __restrict__ x)
{
    __shared__ float Xq[2][32][36], Zq[2][32][36], Xk[2][32][36], Zk[2][32][36];
    __shared__ float wbs[32];

    const int isl = blockIdx.x >> 1, ep = blockIdx.x & 1;
    const int h = blockIdx.y, b = blockIdx.z;
    const int i0  = isl * 32;
    const int e0  = ep * 12;
    const int t   = threadIdx.x;
    const int h32 = h * 32;

    const float* xb = x + (size_t)b * CH * NVOX;
    const float* zb = g_Z + (size_t)b * CH * NVOX;

    if (t < 32) wbs[t] = g_wb[i0 + t];

    const int li  = t >> 3;
    const int lc4 = (t & 7) << 2;
    const int cc  = t >> 3;
    const int d0  = (t & 7) << 2;

    float s[4] = {0.f, 0.f, 0.f, 0.f};
    float dac = 0.f, wac = 0.f;

    const size_t rowoff = (size_t)(i0 + li) * NVOX;
    float4 rq, rzq, rk, rzk;
    {
        const int u = 576 * e0 + h32 + lc4;
        rq  = *(const float4*)(xb + rowoff + u);
        rzq = *(const float4*)(zb + rowoff + u);
        rk  = *(const float4*)(xb + rowoff + u + 192);
        rzk = *(const float4*)(zb + rowoff + u + 192);
    }
    *(float4*)&Xq[0][li][lc4] = rq;  *(float4*)&Zq[0][li][lc4] = rzq;
    *(float4*)&Xk[0][li][lc4] = rk;  *(float4*)&Zk[0][li][lc4] = rzk;
    __syncthreads();

    for (int e = 0; e < 12; e++) {
        const int cur = e & 1, nxt = cur ^ 1;
        if (e < 11) {
            const int u = 576 * (e0 + e + 1) + h32 + lc4;
            rq  = *(const float4*)(xb + rowoff + u);
            rzq = *(const float4*)(zb + rowoff + u);
            rk  = *(const float4*)(xb + rowoff + u + 192);
            rzk = *(const float4*)(zb + rowoff + u + 192);
        }
#pragma unroll
        for (int i = 0; i < 32; i++) {
            const float qv = Xq[cur][i][cc];
            const float4 zv = *(const float4*)&Zk[cur][i][d0];
            s[0] += qv * zv.x; s[1] += qv * zv.y; s[2] += qv * zv.z; s[3] += qv * zv.w;
        }
        if (t < 32) {
#pragma unroll
            for (int i = 0; i < 32; i++) {
                const float xv = Xq[cur][i][t];
                dac += xv * Zq[cur][i][t];
                wac += wbs[i] * xv;
            }
        } else if (t < 64) {
            const int c = t - 32;
#pragma unroll
            for (int i = 0; i < 32; i++) {
                const float xv = Xk[cur][i][c];
                dac += xv * Zk[cur][i][c];
                wac += wbs[i] * xv;
            }
        }
        if (e < 11) {
            *(float4*)&Xq[nxt][li][lc4] = rq;  *(float4*)&Zq[nxt][li][lc4] = rzq;
            *(float4*)&Xk[nxt][li][lc4] = rk;  *(float4*)&Zk[nxt][li][lc4] = rzk;
        }
        __syncthreads();
    }

    float* sp = g_spart + (size_t)((b * HEADS + h) * 12 + blockIdx.x) * 1152;
    sp[cc * 32 + d0 + 0] = s[0];
    sp[cc * 32 + d0 + 1] = s[1];
    sp[cc * 32 + d0 + 2] = s[2];
    sp[cc * 32 + d0 + 3] = s[3];
    if (t < 32)       { sp[1024 + t] = dac; sp[1088 + t] = wac; }
    else if (t < 64)  { sp[1056 + (t - 32)] = dac; sp[1120 + (t - 32)] = wac; }
}

// ---------------------------------------------------------------------------
// K4: reduce partials, assemble S + bias terms, normalize, softmax -> attn
// ---------------------------------------------------------------------------
__global__ __launch_bounds__(256) void softmax_kernel(const float* __restrict__ temp)
{
    __shared__ float sS[1024];
    __shared__ float snq[32], snk[32], swq[32], swk[32];

    const int h = blockIdx.x, b = blockIdx.y;
    const int t = threadIdx.x;
    const float b2 = g_c[0];
    const float* sp = g_spart + (size_t)((b * HEADS + h) * 12) * 1152;

#pragma unroll
    for (int i = 0; i < 4; i++) {
        const int e = t + i * 256;
        float a = 0.f;
        for (int s = 0; s < 12; s++) a += sp[s * 1152 + e];
        sS[e] = a;
    }
    if (t < 64) {
        float d = 0.f, wv = 0.f;
        const int od = 1024 + t, ow = 1088 + t;
        for (int s = 0; s < 12; s++) { d += sp[s * 1152 + od]; wv += sp[s * 1152 + ow]; }
        const float n2 = d + 2.f * wv + 24.f * b2;
        const float r = fmaxf(sqrtf(fmaxf(n2, 0.f)), EPSN);
        if (t < 32) { snq[t] = r; swq[t] = wv; }
        else        { snk[t - 32] = r; swk[t - 32] = wv; }
    }
    __syncthreads();

    const int w = t >> 5, lane = t & 31;
    const float tv = temp[h];
    float* ab = g_attn + (size_t)((b * HEADS + h) * HD) * HD;

    for (int r = 0; r < 4; r++) {
        const int c = w * 4 + r;
        const float Sfull = sS[c * 32 + lane] + swq[c] + swk[lane] + 24.f * b2;
        float L = Sfull / (snq[c] * snk[lane]) * tv;
        float mx = L;
#pragma unroll
        for (int o = 16; o > 0; o >>= 1) mx = fmaxf(mx, __shfl_xor_sync(0xffffffffu, mx, o));
        const float ev = expf(L - mx);
        float sm = ev;
#pragma unroll
        for (int o = 16; o > 0; o >>= 1) sm += __shfl_xor_sync(0xffffffffu, sm, o);
        ab[c * 32 + lane] = ev / sm;
    }
}

// ---------------------------------------------------------------------------
// K5: M[b][o][h*32+d] = sum_cc pwT[cc*6+h][o] * attn[b,h,cc,d]
// Loop-interchanged: float4 LDS of att rows, 32 accumulators.
// ---------------------------------------------------------------------------
__global__ __launch_bounds__(192) void mmix_kernel()
{
    __shared__ float att[32][32];
    const int h = blockIdx.x, b = blockIdx.y;
    const int t = threadIdx.x;

    const float* ab = g_attn + (size_t)((b * HEADS + h) * HD) * HD;
    for (int e = t; e < 1024; e += 192) att[e >> 5][e & 31] = ab[e];
    __syncthreads();

    float s[32];
#pragma unroll
    for (int d = 0; d < 32; d++) s[d] = 0.f;

#pragma unroll 8
    for (int cc = 0; cc < 32; cc++) {
        const float v = g_pwT[(cc * HEADS + h) * CH + t];
#pragma unroll
        for (int d4 = 0; d4 < 8; d4++) {
            const float4 a = *(const float4*)&att[cc][d4 * 4];
            s[d4 * 4 + 0] += v * a.x;
            s[d4 * 4 + 1] += v * a.y;
            s[d4 * 4 + 2] += v * a.z;
            s[d4 * 4 + 3] += v * a.w;
        }
    }

    float* Mb = g_M + (size_t)b * CH * CH + t * CH + h * HD;
#pragma unroll
    for (int d = 0; d < 32; d++) Mb[d] = s[d];
}

// ---------------------------------------------------------------------------
// K6: y[b] = M[b] @ Vbuf[b]^T + proj_b.  BM=192, BN=96, 256 thr, 2 CTA/SM.
// B n-major (Bs[n][20]).
// ---------------------------------------------------------------------------
__global__ __launch_bounds__(256, 2) void out_gemm(float* __restrict__ y,
                                                   const float* __restrict__ pbias)
{
    __shared__ unsigned As[2][192 * 20];
    __shared__ unsigned Bs[2][96 * 20];

    const int b  = blockIdx.z;
    const int n0 = blockIdx.x * 96;
    const int t  = threadIdx.x;
    const int wid = t >> 5, lane = t & 31;
    const int wm = wid & 3, wn = wid >> 2;
    const int gid = lane >> 2, tid4 = lane & 3;

    const float* Mb = g_M + (size_t)b * CH * CH;
    const float* vb = g_V + (size_t)b * NVOX * CH;
    float* yb = y + (size_t)b * CH * NVOX;

    float acc[3][6][4];
#pragma unroll
    for (int i = 0; i < 3; i++)
#pragma unroll
        for (int q = 0; q < 6; q++)
#pragma unroll
            for (int r = 0; r < 4; r++) acc[i][q][r] = 0.f;

    float4 ar[3], br[2];
#define LDA_O(K0) { _Pragma("unroll") for (int l = 0; l < 3; l++) {                      \
                      const int idx = l * 256 + t;                                       \
                      ar[l] = *(const float4*)(Mb + (size_t)(idx >> 2) * CH + (K0) + (idx & 3) * 4); } }
#define LDB_O(K0) { _Pragma("unroll") for (int l = 0; l < 2; l++) {                      \
                      const int idx = l * 256 + t;                                       \
                      if (idx < 384)                                                     \
                        br[l] = *(const float4*)(vb + (size_t)(n0 + (idx >> 2)) * CH + (K0) + (idx & 3) * 4); } }
#define STB_O(ST) { _Pragma("unroll") for (int l = 0; l < 2; l++) {                      \
                      const int idx = l * 256 + t;                                       \
                      if (idx < 384) {                                                   \
                        unsigned* d = &Bs[ST][(idx >> 2) * 20 + (idx & 3) * 4];          \
                        d[0]=f2tf(br[l].x); d[1]=f2tf(br[l].y); d[2]=f2tf(br[l].z); d[3]=f2tf(br[l].w); } } }

    LDA_O(0); LDB_O(0);
    STA_G(0); STB_O(0);
    LDA_O(16); LDB_O(16);
    __syncthreads();

    for (int it = 0; it < 12; it++) {
        const int st = it & 1;
        if (it < 11) { STA_G(st ^ 1); STB_O(st ^ 1); }
        if (it < 10) { LDA_O(16 * (it + 2)); LDB_O(16 * (it + 2)); }

        const unsigned* Asl = As[st];
        const unsigned* Bsl = Bs[st];
#pragma unroll
        for (int h = 0; h < 2; h++) {
            const int kk = h * 8;
            unsigned af[3][4], bf[6][2];
#pragma unroll
            for (int mt = 0; mt < 3; mt++) {
                const int row = wm * 48 + mt * 16 + gid;
                af[mt][0] = Asl[row * 20 + kk + tid4];
                af[mt][1] = Asl[(row + 8) * 20 + kk + tid4];
                af[mt][2] = Asl[row * 20 + kk + tid4 + 4];
                af[mt][3] = Asl[(row + 8) * 20 + kk + tid4 + 4];
            }
#pragma unroll
            for (int nt = 0; nt < 6; nt++) {
                const int col = wn * 48 + nt * 8 + gid;
                bf[nt][0] = Bsl[col * 20 + kk + tid4];
                bf[nt][1] = Bsl[col * 20 + kk + tid4 + 4];
            }
#pragma unroll
            for (int mt = 0; mt < 3; mt++)
#pragma unroll
                for (int nt = 0; nt < 6; nt++)
                    mma_tf32(acc[mt][nt], af[mt], bf[nt]);
        }
        __syncthreads();
    }

#pragma unroll
    for (int mt = 0; mt < 3; mt++) {
        const int r0 = wm * 48 + mt * 16 + gid;
        const float b0 = pbias[r0], b1 = pbias[r0 + 8];
#pragma unroll
        for (int nt = 0; nt < 6; nt++) {
            const int col = n0 + wn * 48 + nt * 8 + 2 * tid4;
            *(float2*)(yb + (size_t)r0 * NVOX + col) =
                make_float2(acc[mt][nt][0] + b0, acc[mt][nt][1] + b0);
            *(float2*)(yb + (size_t)(r0 + 8) * NVOX + col) =
                make_float2(acc[mt][nt][2] + b1, acc[mt][nt][3] + b1);
        }
    }
}

// ---------------------------------------------------------------------------
extern "C" void kernel_launch(void* const* d_in, const int* in_sizes, int n_in,
                              void* d_out, int out_size)
{
    const float* x      = (const float*)d_in[0];
    const float* qkv_w  = (const float*)d_in[1];
    const float* qkv_b  = (const float*)d_in[2];
    const float* temp   = (const float*)d_in[3];
    const float* proj_w = (const float*)d_in[4];
    const float* proj_b = (const float*)d_in[5];
    float* y = (float*)d_out;

    pre_kernel    <<<73, 256>>>(qkv_w, qkv_b, proj_w);

    z_gemm        <<<dim3(96, 1, BATCH), 256>>>(x);
    v_gemm        <<<dim3(48, 3, BATCH), 256>>>(x, qkv_w, qkv_b);
    scores_kernel <<<dim3(12, HEADS, BATCH), 256>>>(x);
    softmax_kernel<<<dim3(HEADS, BATCH), 256>>>(temp);
    mmix_kernel   <<<dim3(HEADS, BATCH), 192>>>();
    out_gemm      <<<dim3(144, 1, BATCH), 256>>>(y, proj_b);
}

// round 11
// speedup vs baseline: 1.1621x; 1.0303x over previous
#include <cuda_runtime.h>
#include <math.h>
#include <stdint.h>

#define BATCH  8
#define CH     192
#define C3     576
#define NVOX   13824       // 24*24*24
#define HEADS  6
#define HD     32
#define EPSN   1e-12f

// Scratch
__device__ float g_Z[(size_t)BATCH * CH * NVOX];     // Z = Gw @ X (only q/k cols valid)
__device__ float g_V[(size_t)BATCH * NVOX * CH];     // Vbuf
__device__ float g_Gw[CH * CH];
__device__ float g_wb[CH];
__device__ float g_pwT[CH * CH];
__device__ float g_c[4];                             // [0] = b2
__device__ float g_spart[BATCH * HEADS * 12 * 1152];
__device__ float g_attn[BATCH * HEADS * HD * HD];
__device__ float g_M[BATCH * CH * CH];

// ---------------------------------------------------------------------------
__device__ __forceinline__ unsigned f2tf(float f) {
    unsigned u;
    asm("cvt.rna.tf32.f32 %0, %1;" : "=r"(u) : "f"(f));
    return u;
}
__device__ __forceinline__ void mma_tf32(float* c, const unsigned* a, const unsigned* b) {
    asm volatile(
        "mma.sync.aligned.m16n8k8.row.col.f32.tf32.tf32.f32 "
        "{%0,%1,%2,%3},{%4,%5,%6,%7},{%8,%9},{%0,%1,%2,%3};"
        : "+f"(c[0]), "+f"(c[1]), "+f"(c[2]), "+f"(c[3])
        : "r"(a[0]), "r"(a[1]), "r"(a[2]), "r"(a[3]), "r"(b[0]), "r"(b[1]));
}
__device__ __forceinline__ uint32_t smem_u32(const void* p) {
    uint32_t a;
    asm("{ .reg .u64 t; cvta.to.shared.u64 t, %1; cvt.u32.u64 %0, t; }" : "=r"(a) : "l"(p));
    return a;
}
__device__ __forceinline__ void cp16(uint32_t dst, const void* src) {
    asm volatile("cp.async.cg.shared.global [%0], [%1], 16;" :: "r"(dst), "l"(src));
}
#define CP_COMMIT() asm volatile("cp.async.commit_group;" ::: "memory")
#define CP_WAIT1()  asm volatile("cp.async.wait_group 1;" ::: "memory")

// ---------------------------------------------------------------------------
// K0 merged prekernel: blocks 0..35 Gw tiles; 36..71 pwT tiles; 72 wb+b2.
// ---------------------------------------------------------------------------
__global__ __launch_bounds__(256) void pre_kernel(const float* __restrict__ w,
                                                  const float* __restrict__ beta,
                                                  const float* __restrict__ pw)
{
    __shared__ float sh[2112];
    const int bid = blockIdx.x;
    const int t = threadIdx.x;

    if (bid < 36) {
        float (*Wi)[33] = (float (*)[33])sh;
        float (*Wj)[33] = (float (*)[33])(sh + 1056);
        const int i0 = (bid % 6) * 32, j0 = (bid / 6) * 32;
        const int ti = t & 31, tj = (t >> 5) * 4;
        float acc[4] = {0.f, 0.f, 0.f, 0.f};
        for (int a0 = 0; a0 < C3; a0 += 32) {
            __syncthreads();
#pragma unroll
            for (int l = 0; l < 4; l++) {
                const int a = (t >> 5) + 8 * l, c = t & 31;
                Wi[a][c] = w[(a0 + a) * CH + i0 + c];
                Wj[a][c] = w[(a0 + a) * CH + j0 + c];
            }
            __syncthreads();
#pragma unroll
            for (int a = 0; a < 32; a++) {
                const float wi = Wi[a][ti];
#pragma unroll
                for (int r = 0; r < 4; r++) acc[r] += wi * Wj[a][tj + r];
            }
        }
#pragma unroll
        for (int r = 0; r < 4; r++) g_Gw[(i0 + ti) * CH + j0 + tj + r] = acc[r];
    } else if (bid < 72) {
        float (*tile)[33] = (float (*)[33])sh;
        const int bb = bid - 36;
        const int bx = (bb % 6) * 32, by = (bb / 6) * 32;
        const int tx = t & 31, ty = t >> 5;
#pragma unroll
        for (int l = 0; l < 4; l++)
            tile[ty + 8 * l][tx] = pw[(by + ty + 8 * l) * CH + bx + tx];
        __syncthreads();
#pragma unroll
        for (int l = 0; l < 4; l++)
            g_pwT[(bx + ty + 8 * l) * CH + by + tx] = tile[tx][ty + 8 * l];
    } else {
        if (t < CH) {
            float s = 0.f;
            for (int a = 0; a < C3; a++) s += beta[a] * w[a * CH + t];
            g_wb[t] = s;
        }
        if (t < 64) {
            float p = 0.f;
            for (int a = t; a < C3; a += 64) p += beta[a] * beta[a];
            sh[t] = p;
        }
        __syncthreads();
        if (t == 0) {
            float s = 0.f;
            for (int i = 0; i < 64; i++) s += sh[i];
            g_c[0] = s;
        }
    }
}

// ---------------------------------------------------------------------------
// K1: Z[b] = Gw @ X[b], columns 576e + 96j, j<4.
// BM=192, BN=96, BK=16, 256 thr, warp 48x48, 2 CTA/SM.
// cp.async 3-stage ring (fp32 staged, cvt at frag load).
// Stage layout: A s*3840 floats (192x20), B s*1664 (16x104).
// ---------------------------------------------------------------------------
#define ZV_SMEM ((3 * 3840 + 3 * 1664) * 4)

__global__ __launch_bounds__(256, 2) void z_gemm(const float* __restrict__ x)
{
    extern __shared__ float zsm[];
    float* Asm = zsm;
    float* Bsm = zsm + 11520;

    const int b = blockIdx.z;
    const int e = blockIdx.x >> 2, j = blockIdx.x & 3;
    const int n0 = 576 * e + 96 * j;
    const int t = threadIdx.x;
    const int wid = t >> 5, lane = t & 31;
    const int wm = wid & 3, wn = wid >> 2;
    const int gid = lane >> 2, tid4 = lane & 3;

    const float* bsrc = x + (size_t)b * CH * NVOX + n0;
    float* zb = g_Z + (size_t)b * CH * NVOX + n0;

    const uint32_t sA = smem_u32(Asm);
    const uint32_t sB = smem_u32(Bsm);

    float acc[3][6][4];
#pragma unroll
    for (int i = 0; i < 3; i++)
#pragma unroll
        for (int q = 0; q < 6; q++)
#pragma unroll
            for (int r = 0; r < 4; r++) acc[i][q][r] = 0.f;

#define ZISSUE(K0, S) do {                                                              \
    _Pragma("unroll") for (int l = 0; l < 3; l++) {                                     \
        const int idx = l * 256 + t;                                                    \
        const int r = idx >> 2, q = idx & 3;                                            \
        cp16(sA + (uint32_t)(((S) * 3840 + r * 20 + q * 4) * 4),                        \
             g_Gw + r * CH + (K0) + q * 4);                                             \
    }                                                                                   \
    _Pragma("unroll") for (int l = 0; l < 2; l++) {                                     \
        const int idx = l * 256 + t;                                                    \
        if (idx < 384) {                                                                \
            const int r = idx / 24, c = idx % 24;                                       \
            cp16(sB + (uint32_t)(((S) * 1664 + r * 104 + c * 4) * 4),                   \
                 bsrc + (size_t)((K0) + r) * NVOX + c * 4);                             \
        }                                                                               \
    } } while (0)

    ZISSUE(0, 0);  CP_COMMIT();
    ZISSUE(16, 1); CP_COMMIT();

    for (int it = 0; it < 12; it++) {
        CP_WAIT1();
        __syncthreads();
        if (it < 10) { ZISSUE(16 * (it + 2), (it + 2) % 3); }
        CP_COMMIT();

        const float* Asl = Asm + (it % 3) * 3840;
        const float* Bsl = Bsm + (it % 3) * 1664;
#pragma unroll
        for (int h = 0; h < 2; h++) {
            const int kk = h * 8;
            unsigned af[3][4], bf[6][2];
#pragma unroll
            for (int mt = 0; mt < 3; mt++) {
                const int row = wm * 48 + mt * 16 + gid;
                af[mt][0] = f2tf(Asl[row * 20 + kk + tid4]);
                af[mt][1] = f2tf(Asl[(row + 8) * 20 + kk + tid4]);
                af[mt][2] = f2tf(Asl[row * 20 + kk + tid4 + 4]);
                af[mt][3] = f2tf(Asl[(row + 8) * 20 + kk + tid4 + 4]);
            }
#pragma unroll
            for (int nt = 0; nt < 6; nt++) {
                const int col = wn * 48 + nt * 8 + gid;
                bf[nt][0] = f2tf(Bsl[(kk + tid4) * 104 + col]);
                bf[nt][1] = f2tf(Bsl[(kk + tid4 + 4) * 104 + col]);
            }
#pragma unroll
            for (int mt = 0; mt < 3; mt++)
#pragma unroll
                for (int nt = 0; nt < 6; nt++)
                    mma_tf32(acc[mt][nt], af[mt], bf[nt]);
        }
    }

#pragma unroll
    for (int mt = 0; mt < 3; mt++) {
        const int r0 = wm * 48 + mt * 16 + gid;
#pragma unroll
        for (int nt = 0; nt < 6; nt++) {
            const int col = wn * 48 + nt * 8 + 2 * tid4;
            *(float2*)(zb + (size_t)r0 * NVOX + col) = make_float2(acc[mt][nt][0], acc[mt][nt][1]);
            *(float2*)(zb + (size_t)(r0 + 8) * NVOX + col) = make_float2(acc[mt][nt][2], acc[mt][nt][3]);
        }
    }
}

// ---------------------------------------------------------------------------
// K2: Vbuf = W[m0:m0+192] @ Xv(e, 96j) + beta.  cp.async 3-stage, same layout.
// ---------------------------------------------------------------------------
__global__ __launch_bounds__(256, 2) void v_gemm(const float* __restrict__ x,
                                                 const float* __restrict__ qkv_w,
                                                 const float* __restrict__ beta)
{
    extern __shared__ float zsm[];
    float* Asm = zsm;
    float* Bsm = zsm + 11520;

    const int b = blockIdx.z;
    const int e = blockIdx.x >> 1, j = blockIdx.x & 1;
    const int m0 = blockIdx.y * 192;
    const int t = threadIdx.x;
    const int wid = t >> 5, lane = t & 31;
    const int wm = wid & 3, wn = wid >> 2;
    const int gid = lane >> 2, tid4 = lane & 3;

    const float* bsrc = x + (size_t)b * CH * NVOX + 576 * e + 384 + 96 * j;
    const float* Asrc = qkv_w + (size_t)m0 * CH;
    float* vb = g_V + (size_t)b * NVOX * CH;

    const uint32_t sA = smem_u32(Asm);
    const uint32_t sB = smem_u32(Bsm);

    float acc[3][6][4];
#pragma unroll
    for (int i = 0; i < 3; i++)
#pragma unroll
        for (int q = 0; q < 6; q++)
#pragma unroll
            for (int r = 0; r < 4; r++) acc[i][q][r] = 0.f;

#define VISSUE(K0, S) do {                                                              \
    _Pragma("unroll") for (int l = 0; l < 3; l++) {                                     \
        const int idx = l * 256 + t;                                                    \
        const int r = idx >> 2, q = idx & 3;                                            \
        cp16(sA + (uint32_t)(((S) * 3840 + r * 20 + q * 4) * 4),                        \
             Asrc + (size_t)r * CH + (K0) + q * 4);                                     \
    }                                                                                   \
    _Pragma("unroll") for (int l = 0; l < 2; l++) {                                     \
        const int idx = l * 256 + t;                                                    \
        if (idx < 384) {                                                                \
            const int r = idx / 24, c = idx % 24;                                       \
            cp16(sB + (uint32_t)(((S) * 1664 + r * 104 + c * 4) * 4),                   \
                 bsrc + (size_t)((K0) + r) * NVOX + c * 4);                             \
        }                                                                               \
    } } while (0)

    VISSUE(0, 0);  CP_COMMIT();
    VISSUE(16, 1); CP_COMMIT();

    for (int it = 0; it < 12; it++) {
        CP_WAIT1();
        __syncthreads();
        if (it < 10) { VISSUE(16 * (it + 2), (it + 2) % 3); }
        CP_COMMIT();

        const float* Asl = Asm + (it % 3) * 3840;
        const float* Bsl = Bsm + (it % 3) * 1664;
#pragma unroll
        for (int h = 0; h < 2; h++) {
            const int kk = h * 8;
            unsigned af[3][4], bf[6][2];
#pragma unroll
            for (int mt = 0; mt < 3; mt++) {
                const int row = wm * 48 + mt * 16 + gid;
                af[mt][0] = f2tf(Asl[row * 20 + kk + tid4]);
                af[mt][1] = f2tf(Asl[(row + 8) * 20 + kk + tid4]);
                af[mt][2] = f2tf(Asl[row * 20 + kk + tid4 + 4]);
                af[mt][3] = f2tf(Asl[(row + 8) * 20 + kk + tid4 + 4]);
            }
#pragma unroll
            for (int nt = 0; nt < 6; nt++) {
                const int col = wn * 48 + nt * 8 + gid;
                bf[nt][0] = f2tf(Bsl[(kk + tid4) * 104 + col]);
                bf[nt][1] = f2tf(Bsl[(kk + tid4 + 4) * 104 + col]);
            }
#pragma unroll
            for (int mt = 0; mt < 3; mt++)
#pragma unroll
                for (int nt = 0; nt < 6; nt++)
                    mma_tf32(acc[mt][nt], af[mt], bf[nt]);
        }
    }

#pragma unroll
    for (int mt = 0; mt < 3; mt++) {
        const int r0 = m0 + wm * 48 + mt * 16 + gid;
        const float b0 = beta[r0], b1 = beta[r0 + 8];
#pragma unroll
        for (int nt = 0; nt < 6; nt++) {
            const int pc = e * 192 + 96 * j + wn * 48 + nt * 8 + 2 * tid4;
            *(float2*)(vb + (size_t)r0 * 4608 + pc) =
                make_float2(acc[mt][nt][0] + b0, acc[mt][nt][1] + b0);
            *(float2*)(vb + (size_t)(r0 + 8) * 4608 + pc) =
                make_float2(acc[mt][nt][2] + b1, acc[mt][nt][3] + b1);
        }
    }
}

// ---------------------------------------------------------------------------
// K3: score partials v2. grid (12, H, B), 256 thr.
// Warps 0-3: S compute, 4cc x 4d register block, i-halves split across warps.
// Warp 4: q-diag + wbq; warp 5: k-diag + wbk.
// ---------------------------------------------------------------------------
__global__ __launch_bounds__(256) void scores_kernel(const float* __restrict__ x)
{
    __shared__ float Xq[2][32][36], Zq[2][32][36], Xk[2][32][36], Zk[2][32][36];
    __shared__ float wbs[32];
    __shared__ float Sh[2][32][32];

    const int isl = blockIdx.x >> 1, ep = blockIdx.x & 1;
    const int h = blockIdx.y, b = blockIdx.z;
    const int i0 = isl * 32, e0 = ep * 12;
    const int t = threadIdx.x;
    const int wid = t >> 5, lane = t & 31;
    const int h32 = h * 32;

    const float* xb = x + (size_t)b * CH * NVOX;
    const float* zb = g_Z + (size_t)b * CH * NVOX;

    if (t < 32) wbs[t] = g_wb[i0 + t];

    // loader mapping (all threads)
    const int li  = t >> 3;
    const int lc4 = (t & 7) << 2;

    // compute mapping (warps 0-3)
    const int ihalf = wid >> 1;
    const int sig = (wid & 1) * 32 + lane;
    const int ccg = sig >> 3;
    const int d0c = (sig & 7) << 2;

    float s[4][4];
#pragma unroll
    for (int a = 0; a < 4; a++)
#pragma unroll
        for (int q = 0; q < 4; q++) s[a][q] = 0.f;
    float dac = 0.f, wac = 0.f;

    const size_t rowoff = (size_t)(i0 + li) * NVOX;
    float4 rq, rzq, rk, rzk;
    {
        const int u = 576 * e0 + h32 + lc4;
        rq  = *(const float4*)(xb + rowoff + u);
        rzq = *(const float4*)(zb + rowoff + u);
        rk  = *(const float4*)(xb + rowoff + u + 192);
        rzk = *(const float4*)(zb + rowoff + u + 192);
    }
    *(float4*)&Xq[0][li][lc4] = rq;  *(float4*)&Zq[0][li][lc4] = rzq;
    *(float4*)&Xk[0][li][lc4] = rk;  *(float4*)&Zk[0][li][lc4] = rzk;
    __syncthreads();

    for (int e = 0; e < 12; e++) {
        const int cur = e & 1, nxt = cur ^ 1;
        if (e < 11) {
            const int u = 576 * (e0 + e + 1) + h32 + lc4;
            rq  = *(const float4*)(xb + rowoff + u);
            rzq = *(const float4*)(zb + rowoff + u);
            rk  = *(const float4*)(xb + rowoff + u + 192);
            rzk = *(const float4*)(zb + rowoff + u + 192);
        }
        if (wid < 4) {
            const int ib = ihalf * 16;
#pragma unroll
            for (int ii = 0; ii < 16; ii++) {
                const int i = ib + ii;
                const float4 zv = *(const float4*)&Zk[cur][i][d0c];
                const float q0 = Xq[cur][i][ccg];
                const float q1 = Xq[cur][i][ccg + 8];
                const float q2 = Xq[cur][i][ccg + 16];
                const float q3 = Xq[cur][i][ccg + 24];
                s[0][0] += q0 * zv.x; s[0][1] += q0 * zv.y; s[0][2] += q0 * zv.z; s[0][3] += q0 * zv.w;
                s[1][0] += q1 * zv.x; s[1][1] += q1 * zv.y; s[1][2] += q1 * zv.z; s[1][3] += q1 * zv.w;
                s[2][0] += q2 * zv.x; s[2][1] += q2 * zv.y; s[2][2] += q2 * zv.z; s[2][3] += q2 * zv.w;
                s[3][0] += q3 * zv.x; s[3][1] += q3 * zv.y; s[3][2] += q3 * zv.z; s[3][3] += q3 * zv.w;
            }
        } else if (wid == 4) {
#pragma unroll
            for (int i = 0; i < 32; i++) {
                const float xv = Xq[cur][i][lane];
                dac += xv * Zq[cur][i][lane];
                wac += wbs[i] * xv;
            }
        } else if (wid == 5) {
#pragma unroll
            for (int i = 0; i < 32; i++) {
                const float xv = Xk[cur][i][lane];
                dac += xv * Zk[cur][i][lane];
                wac += wbs[i] * xv;
            }
        }
        if (e < 11) {
            *(float4*)&Xq[nxt][li][lc4] = rq;  *(float4*)&Zq[nxt][li][lc4] = rzq;
            *(float4*)&Xk[nxt][li][lc4] = rk;  *(float4*)&Zk[nxt][li][lc4] = rzk;
        }
        __syncthreads();
    }

    if (wid < 4) {
#pragma unroll
        for (int a = 0; a < 4; a++)
            *(float4*)&Sh[ihalf][ccg + 8 * a][d0c] =
                make_float4(s[a][0], s[a][1], s[a][2], s[a][3]);
    }
    __syncthreads();

    float* sp = g_spart + (size_t)((b * HEADS + h) * 12 + blockIdx.x) * 1152;
    {
        const int eidx = t * 4;
        const float* s0 = &Sh[0][0][0];
        const float* s1 = &Sh[1][0][0];
        float4 a = *(const float4*)(s0 + eidx);
        float4 c = *(const float4*)(s1 + eidx);
        sp[eidx + 0] = a.x + c.x;
        sp[eidx + 1] = a.y + c.y;
        sp[eidx + 2] = a.z + c.z;
        sp[eidx + 3] = a.w + c.w;
    }
    if (wid == 4) { sp[1024 + lane] = dac; sp[1088 + lane] = wac; }
    if (wid == 5) { sp[1056 + lane] = dac; sp[1120 + lane] = wac; }
}

// ---------------------------------------------------------------------------
// K4: reduce partials, assemble S + bias terms, normalize, softmax -> attn
// ---------------------------------------------------------------------------
__global__ __launch_bounds__(256) void softmax_kernel(const float* __restrict__ temp)
{
    __shared__ float sS[1024];
    __shared__ float snq[32], snk[32], swq[32], swk[32];

    const int h = blockIdx.x, b = blockIdx.y;
    const int t = threadIdx.x;
    const float b2 = g_c[0];
    const float* sp = g_spart + (size_t)((b * HEADS + h) * 12) * 1152;

#pragma unroll
    for (int i = 0; i < 4; i++) {
        const int e = t + i * 256;
        float a = 0.f;
        for (int s = 0; s < 12; s++) a += sp[s * 1152 + e];
        sS[e] = a;
    }
    if (t < 64) {
        float d = 0.f, wv = 0.f;
        const int od = 1024 + t, ow = 1088 + t;
        for (int s = 0; s < 12; s++) { d += sp[s * 1152 + od]; wv += sp[s * 1152 + ow]; }
        const float n2 = d + 2.f * wv + 24.f * b2;
        const float r = fmaxf(sqrtf(fmaxf(n2, 0.f)), EPSN);
        if (t < 32) { snq[t] = r; swq[t] = wv; }
        else        { snk[t - 32] = r; swk[t - 32] = wv; }
    }
    __syncthreads();

    const int w = t >> 5, lane = t & 31;
    const float tv = temp[h];
    float* ab = g_attn + (size_t)((b * HEADS + h) * HD) * HD;

    for (int r = 0; r < 4; r++) {
        const int c = w * 4 + r;
        const float Sfull = sS[c * 32 + lane] + swq[c] + swk[lane] + 24.f * b2;
        float L = Sfull / (snq[c] * snk[lane]) * tv;
        float mx = L;
#pragma unroll
        for (int o = 16; o > 0; o >>= 1) mx = fmaxf(mx, __shfl_xor_sync(0xffffffffu, mx, o));
        const float ev = expf(L - mx);
        float sm = ev;
#pragma unroll
        for (int o = 16; o > 0; o >>= 1) sm += __shfl_xor_sync(0xffffffffu, sm, o);
        ab[c * 32 + lane] = ev / sm;
    }
}

// ---------------------------------------------------------------------------
// K5: M[b][o][h*32+d] = sum_cc pwT[cc*6+h][o] * attn[b,h,cc,d]
// ---------------------------------------------------------------------------
__global__ __launch_bounds__(192) void mmix_kernel()
{
    __shared__ float att[32][32];
    const int h = blockIdx.x, b = blockIdx.y;
    const int t = threadIdx.x;

    const float* ab = g_attn + (size_t)((b * HEADS + h) * HD) * HD;
    for (int e = t; e < 1024; e += 192) att[e >> 5][e & 31] = ab[e];
    __syncthreads();

    float s[32];
#pragma unroll
    for (int d = 0; d < 32; d++) s[d] = 0.f;

#pragma unroll 8
    for (int cc = 0; cc < 32; cc++) {
        const float v = g_pwT[(cc * HEADS + h) * CH + t];
#pragma unroll
        for (int d4 = 0; d4 < 8; d4++) {
            const float4 a = *(const float4*)&att[cc][d4 * 4];
            s[d4 * 4 + 0] += v * a.x;
            s[d4 * 4 + 1] += v * a.y;
            s[d4 * 4 + 2] += v * a.z;
            s[d4 * 4 + 3] += v * a.w;
        }
    }

    float* Mb = g_M + (size_t)b * CH * CH + t * CH + h * HD;
#pragma unroll
    for (int d = 0; d < 32; d++) Mb[d] = s[d];
}

// ---------------------------------------------------------------------------
// K6: y[b] = M[b] @ Vbuf[b]^T + proj_b.  BM=192, BN=96, 256 thr, 2 CTA/SM.
// (round-10 proven version, renamed macros)
// ---------------------------------------------------------------------------
__global__ __launch_bounds__(256, 2) void out_gemm(float* __restrict__ y,
                                                   const float* __restrict__ pbias)
{
    __shared__ unsigned As[2][192 * 20];
    __shared__ unsigned Bs[2][96 * 20];

    const int b  = blockIdx.z;
    const int n0 = blockIdx.x * 96;
    const int t  = threadIdx.x;
    const int wid = t >> 5, lane = t & 31;
    const int wm = wid & 3, wn = wid >> 2;
    const int gid = lane >> 2, tid4 = lane & 3;

    const float* Mb = g_M + (size_t)b * CH * CH;
    const float* vb = g_V + (size_t)b * NVOX * CH;
    float* yb = y + (size_t)b * CH * NVOX;

    float acc[3][6][4];
#pragma unroll
    for (int i = 0; i < 3; i++)
#pragma unroll
        for (int q = 0; q < 6; q++)
#pragma unroll
            for (int r = 0; r < 4; r++) acc[i][q][r] = 0.f;

    float4 ar[3], br[2];
#define LDA_O(K0) { _Pragma("unroll") for (int l = 0; l < 3; l++) {                      \
                      const int idx = l * 256 + t;                                       \
                      ar[l] = *(const float4*)(Mb + (size_t)(idx >> 2) * CH + (K0) + (idx & 3) * 4); } }
#define LDB_O(K0) { _Pragma("unroll") for (int l = 0; l < 2; l++) {                      \
                      const int idx = l * 256 + t;                                       \
                      if (idx < 384)                                                     \
                        br[l] = *(const float4*)(vb + (size_t)(n0 + (idx >> 2)) * CH + (K0) + (idx & 3) * 4); } }
#define STA_O(ST) { _Pragma("unroll") for (int l = 0; l < 3; l++) {                      \
                      const int idx = l * 256 + t;                                       \
                      unsigned* d = &As[ST][(idx >> 2) * 20 + (idx & 3) * 4];            \
                      d[0]=f2tf(ar[l].x); d[1]=f2tf(ar[l].y); d[2]=f2tf(ar[l].z); d[3]=f2tf(ar[l].w); } }
#define STB_O(ST) { _Pragma("unroll") for (int l = 0; l < 2; l++) {                      \
                      const int idx = l * 256 + t;                                       \
                      if (idx < 384) {                                                   \
                        unsigned* d = &Bs[ST][(idx >> 2) * 20 + (idx & 3) * 4];          \
                        d[0]=f2tf(br[l].x); d[1]=f2tf(br[l].y); d[2]=f2tf(br[l].z); d[3]=f2tf(br[l].w); } } }

    LDA_O(0); LDB_O(0);
    STA_O(0); STB_O(0);
    LDA_O(16); LDB_O(16);
    __syncthreads();

    for (int it = 0; it < 12; it++) {
        const int st = it & 1;
        if (it < 11) { STA_O(st ^ 1); STB_O(st ^ 1); }
        if (it < 10) { LDA_O(16 * (it + 2)); LDB_O(16 * (it + 2)); }

        const unsigned* Asl = As[st];
        const unsigned* Bsl = Bs[st];
#pragma unroll
        for (int h = 0; h < 2; h++) {
            const int kk = h * 8;
            unsigned af[3][4], bf[6][2];
#pragma unroll
            for (int mt = 0; mt < 3; mt++) {
                const int row = wm * 48 + mt * 16 + gid;
                af[mt][0] = Asl[row * 20 + kk + tid4];
                af[mt][1] = Asl[(row + 8) * 20 + kk + tid4];
                af[mt][2] = Asl[row * 20 + kk + tid4 + 4];
                af[mt][3] = Asl[(row + 8) * 20 + kk + tid4 + 4];
            }
#pragma unroll
            for (int nt = 0; nt < 6; nt++) {
                const int col = wn * 48 + nt * 8 + gid;
                bf[nt][0] = Bsl[col * 20 + kk + tid4];
                bf[nt][1] = Bsl[col * 20 + kk + tid4 + 4];
            }
#pragma unroll
            for (int mt = 0; mt < 3; mt++)
#pragma unroll
                for (int nt = 0; nt < 6; nt++)
                    mma_tf32(acc[mt][nt], af[mt], bf[nt]);
        }
        __syncthreads();
    }

#pragma unroll
    for (int mt = 0; mt < 3; mt++) {
        const int r0 = wm * 48 + mt * 16 + gid;
        const float b0 = pbias[r0], b1 = pbias[r0 + 8];
#pragma unroll
        for (int nt = 0; nt < 6; nt++) {
            const int col = n0 + wn * 48 + nt * 8 + 2 * tid4;
            *(float2*)(yb + (size_t)r0 * NVOX + col) =
                make_float2(acc[mt][nt][0] + b0, acc[mt][nt][1] + b0);
            *(float2*)(yb + (size_t)(r0 + 8) * NVOX + col) =
                make_float2(acc[mt][nt][2] + b1, acc[mt][nt][3] + b1);
        }
    }
}

// ---------------------------------------------------------------------------
extern "C" void kernel_launch(void* const* d_in, const int* in_sizes, int n_in,
                              void* d_out, int out_size)
{
    const float* x      = (const float*)d_in[0];
    const float* qkv_w  = (const float*)d_in[1];
    const float* qkv_b  = (const float*)d_in[2];
    const float* temp   = (const float*)d_in[3];
    const float* proj_w = (const float*)d_in[4];
    const float* proj_b = (const float*)d_in[5];
    float* y = (float*)d_out;

    cudaFuncSetAttribute(z_gemm, cudaFuncAttributeMaxDynamicSharedMemorySize, ZV_SMEM);
    cudaFuncSetAttribute(v_gemm, cudaFuncAttributeMaxDynamicSharedMemorySize, ZV_SMEM);

    pre_kernel    <<<73, 256>>>(qkv_w, qkv_b, proj_w);

    z_gemm        <<<dim3(96, 1, BATCH), 256, ZV_SMEM>>>(x);
    v_gemm        <<<dim3(48, 3, BATCH), 256, ZV_SMEM>>>(x, qkv_w, qkv_b);
    scores_kernel <<<dim3(12, HEADS, BATCH), 256>>>(x);
    softmax_kernel<<<dim3(HEADS, BATCH), 256>>>(temp);
    mmix_kernel   <<<dim3(HEADS, BATCH), 192>>>();
    out_gemm      <<<dim3(144, 1, BATCH), 256>>>(y, proj_b);
}

// round 12
// speedup vs baseline: 1.2110x; 1.0421x over previous
#include <cuda_runtime.h>
#include <math.h>
#include <stdint.h>

#define BATCH  8
#define CH     192
#define C3     576
#define NVOX   13824       // 24*24*24
#define HEADS  6
#define HD     32
#define EPSN   1e-12f

// Scratch
__device__ float g_Z[(size_t)BATCH * CH * NVOX];     // Z = Gw @ X (only q/k cols valid)
__device__ float g_V[(size_t)BATCH * NVOX * CH];     // Vbuf
__device__ float g_Gw[CH * CH];
__device__ float g_wb[CH];
__device__ float g_pwT[CH * CH];
__device__ float g_c[4];                             // [0] = b2
__device__ float g_spart[BATCH * HEADS * 12 * 1152];
__device__ float g_attn[BATCH * HEADS * HD * HD];
__device__ float g_M[BATCH * CH * CH];

// ---------------------------------------------------------------------------
__device__ __forceinline__ unsigned f2tf(float f) {
    unsigned u;
    asm("cvt.rna.tf32.f32 %0, %1;" : "=r"(u) : "f"(f));
    return u;
}
__device__ __forceinline__ void mma_tf32(float* c, const unsigned* a, const unsigned* b) {
    asm volatile(
        "mma.sync.aligned.m16n8k8.row.col.f32.tf32.tf32.f32 "
        "{%0,%1,%2,%3},{%4,%5,%6,%7},{%8,%9},{%0,%1,%2,%3};"
        : "+f"(c[0]), "+f"(c[1]), "+f"(c[2]), "+f"(c[3])
        : "r"(a[0]), "r"(a[1]), "r"(a[2]), "r"(a[3]), "r"(b[0]), "r"(b[1]));
}
__device__ __forceinline__ uint32_t smem_u32(const void* p) {
    uint32_t a;
    asm("{ .reg .u64 t; cvta.to.shared.u64 t, %1; cvt.u32.u64 %0, t; }" : "=r"(a) : "l"(p));
    return a;
}
__device__ __forceinline__ void ldsm_x4(unsigned* r, uint32_t addr) {
    asm volatile("ldmatrix.sync.aligned.m8n8.x4.shared.b16 {%0,%1,%2,%3}, [%4];"
        : "=r"(r[0]), "=r"(r[1]), "=r"(r[2]), "=r"(r[3]) : "r"(addr));
}
__device__ __forceinline__ void ldsm_x2(unsigned* r, uint32_t addr) {
    asm volatile("ldmatrix.sync.aligned.m8n8.x2.shared.b16 {%0,%1}, [%2];"
        : "=r"(r[0]), "=r"(r[1]) : "r"(addr));
}

// ---------------------------------------------------------------------------
// K0 merged prekernel: blocks 0..35 Gw tiles; 36..71 pwT tiles; 72 wb+b2.
// ---------------------------------------------------------------------------
__global__ __launch_bounds__(256) void pre_kernel(const float* __restrict__ w,
                                                  const float* __restrict__ beta,
                                                  const float* __restrict__ pw)
{
    __shared__ float sh[2112];
    const int bid = blockIdx.x;
    const int t = threadIdx.x;

    if (bid < 36) {
        float (*Wi)[33] = (float (*)[33])sh;
        float (*Wj)[33] = (float (*)[33])(sh + 1056);
        const int i0 = (bid % 6) * 32, j0 = (bid / 6) * 32;
        const int ti = t & 31, tj = (t >> 5) * 4;
        float acc[4] = {0.f, 0.f, 0.f, 0.f};
        for (int a0 = 0; a0 < C3; a0 += 32) {
            __syncthreads();
#pragma unroll
            for (int l = 0; l < 4; l++) {
                const int a = (t >> 5) + 8 * l, c = t & 31;
                Wi[a][c] = w[(a0 + a) * CH + i0 + c];
                Wj[a][c] = w[(a0 + a) * CH + j0 + c];
            }
            __syncthreads();
#pragma unroll
            for (int a = 0; a < 32; a++) {
                const float wi = Wi[a][ti];
#pragma unroll
                for (int r = 0; r < 4; r++) acc[r] += wi * Wj[a][tj + r];
            }
        }
#pragma unroll
        for (int r = 0; r < 4; r++) g_Gw[(i0 + ti) * CH + j0 + tj + r] = acc[r];
    } else if (bid < 72) {
        float (*tile)[33] = (float (*)[33])sh;
        const int bb = bid - 36;
        const int bx = (bb % 6) * 32, by = (bb / 6) * 32;
        const int tx = t & 31, ty = t >> 5;
#pragma unroll
        for (int l = 0; l < 4; l++)
            tile[ty + 8 * l][tx] = pw[(by + ty + 8 * l) * CH + bx + tx];
        __syncthreads();
#pragma unroll
        for (int l = 0; l < 4; l++)
            g_pwT[(bx + ty + 8 * l) * CH + by + tx] = tile[tx][ty + 8 * l];
    } else {
        if (t < CH) {
            float s = 0.f;
            for (int a = 0; a < C3; a++) s += beta[a] * w[a * CH + t];
            g_wb[t] = s;
        }
        if (t < 64) {
            float p = 0.f;
            for (int a = t; a < C3; a += 64) p += beta[a] * beta[a];
            sh[t] = p;
        }
        __syncthreads();
        if (t == 0) {
            float s = 0.f;
            for (int i = 0; i < 64; i++) s += sh[i];
            g_c[0] = s;
        }
    }
}

// ---------------------------------------------------------------------------
// K1: Z[b] = Gw @ X[b], columns 576e + 96j, j<4.
// BM=192, BN=96, BK=16, 256 thr, warp 48x48, 2 CTA/SM.
// smem holds tf32 bits; A frags via ldmatrix.x4, B frags via LDS (k-major).
// ---------------------------------------------------------------------------
__global__ __launch_bounds__(256, 2) void z_gemm(const float* __restrict__ x)
{
    __shared__ unsigned As[2][192 * 20];
    __shared__ unsigned Bs[2][16 * 104];

    const int b = blockIdx.z;
    const int e = blockIdx.x >> 2, j = blockIdx.x & 3;
    const int n0 = 576 * e + 96 * j;
    const int t = threadIdx.x;
    const int wid = t >> 5, lane = t & 31;
    const int wm = wid & 3, wn = wid >> 2;
    const int gid = lane >> 2, tid4 = lane & 3;

    const float* bsrc = x + (size_t)b * CH * NVOX + n0;
    float* zb = g_Z + (size_t)b * CH * NVOX + n0;

    const uint32_t sAs = smem_u32(As);
    // per-lane ldmatrix offset (words): row part + col part
    const uint32_t aoff = (uint32_t)((((lane & 7) + ((lane >> 3) & 1) * 8) * 20 +
                                      ((lane >> 4) * 4)) * 4);

    float acc[3][6][4];
#pragma unroll
    for (int i = 0; i < 3; i++)
#pragma unroll
        for (int q = 0; q < 6; q++)
#pragma unroll
            for (int r = 0; r < 4; r++) acc[i][q][r] = 0.f;

    float4 ar[3], br[2];
#define LDA_Z(K0) { _Pragma("unroll") for (int l = 0; l < 3; l++) {                      \
                      const int idx = l * 256 + t;                                       \
                      ar[l] = *(const float4*)(g_Gw + (idx >> 2) * CH + (K0) + (idx & 3) * 4); } }
#define LDB_Z(K0) { _Pragma("unroll") for (int l = 0; l < 2; l++) {                      \
                      const int idx = l * 256 + t;                                       \
                      if (idx < 384)                                                     \
                        br[l] = *(const float4*)(bsrc + (size_t)((K0) + idx / 24) * NVOX + (idx % 24) * 4); } }
#define STA_G(ST) { _Pragma("unroll") for (int l = 0; l < 3; l++) {                      \
                      const int idx = l * 256 + t;                                       \
                      unsigned* d = &As[ST][(idx >> 2) * 20 + (idx & 3) * 4];            \
                      d[0]=f2tf(ar[l].x); d[1]=f2tf(ar[l].y); d[2]=f2tf(ar[l].z); d[3]=f2tf(ar[l].w); } }
#define STB_G(ST) { _Pragma("unroll") for (int l = 0; l < 2; l++) {                      \
                      const int idx = l * 256 + t;                                       \
                      if (idx < 384) {                                                   \
                        unsigned* d = &Bs[ST][(idx / 24) * 104 + (idx % 24) * 4];        \
                        d[0]=f2tf(br[l].x); d[1]=f2tf(br[l].y); d[2]=f2tf(br[l].z); d[3]=f2tf(br[l].w); } } }

    LDA_Z(0); LDB_Z(0);
    STA_G(0); STB_G(0);
    LDA_Z(16); LDB_Z(16);
    __syncthreads();

    for (int it = 0; it < 12; it++) {
        const int st = it & 1;
        if (it < 11) { STA_G(st ^ 1); STB_G(st ^ 1); }
        if (it < 10) { LDA_Z(16 * (it + 2)); LDB_Z(16 * (it + 2)); }

        const unsigned* Bsl = Bs[st];
        const uint32_t aBase = sAs + (uint32_t)(st * 3840 * 4) + aoff;
#pragma unroll
        for (int h = 0; h < 2; h++) {
            const int kk = h * 8;
            unsigned af[3][4], bf[6][2];
#pragma unroll
            for (int mt = 0; mt < 3; mt++) {
                const int r0 = wm * 48 + mt * 16;
                ldsm_x4(af[mt], aBase + (uint32_t)((r0 * 20 + kk) * 4));
            }
#pragma unroll
            for (int nt = 0; nt < 6; nt++) {
                const int col = wn * 48 + nt * 8 + gid;
                bf[nt][0] = Bsl[(kk + tid4) * 104 + col];
                bf[nt][1] = Bsl[(kk + tid4 + 4) * 104 + col];
            }
#pragma unroll
            for (int mt = 0; mt < 3; mt++)
#pragma unroll
                for (int nt = 0; nt < 6; nt++)
                    mma_tf32(acc[mt][nt], af[mt], bf[nt]);
        }
        __syncthreads();
    }

#pragma unroll
    for (int mt = 0; mt < 3; mt++) {
        const int r0 = wm * 48 + mt * 16 + gid;
#pragma unroll
        for (int nt = 0; nt < 6; nt++) {
            const int col = wn * 48 + nt * 8 + 2 * tid4;
            *(float2*)(zb + (size_t)r0 * NVOX + col) = make_float2(acc[mt][nt][0], acc[mt][nt][1]);
            *(float2*)(zb + (size_t)(r0 + 8) * NVOX + col) = make_float2(acc[mt][nt][2], acc[mt][nt][3]);
        }
    }
}

// ---------------------------------------------------------------------------
// K2: Vbuf = W[m0:m0+192] @ Xv(e, 96j) + beta.  Same structure as K1.
// ---------------------------------------------------------------------------
__global__ __launch_bounds__(256, 2) void v_gemm(const float* __restrict__ x,
                                                 const float* __restrict__ qkv_w,
                                                 const float* __restrict__ beta)
{
    __shared__ unsigned As[2][192 * 20];
    __shared__ unsigned Bs[2][16 * 104];

    const int b = blockIdx.z;
    const int e = blockIdx.x >> 1, j = blockIdx.x & 1;
    const int m0 = blockIdx.y * 192;
    const int t = threadIdx.x;
    const int wid = t >> 5, lane = t & 31;
    const int wm = wid & 3, wn = wid >> 2;
    const int gid = lane >> 2, tid4 = lane & 3;

    const float* bsrc = x + (size_t)b * CH * NVOX + 576 * e + 384 + 96 * j;
    const float* Asrc = qkv_w + (size_t)m0 * CH;
    float* vb = g_V + (size_t)b * NVOX * CH;

    const uint32_t sAs = smem_u32(As);
    const uint32_t aoff = (uint32_t)((((lane & 7) + ((lane >> 3) & 1) * 8) * 20 +
                                      ((lane >> 4) * 4)) * 4);

    float acc[3][6][4];
#pragma unroll
    for (int i = 0; i < 3; i++)
#pragma unroll
        for (int q = 0; q < 6; q++)
#pragma unroll
            for (int r = 0; r < 4; r++) acc[i][q][r] = 0.f;

    float4 ar[3], br[2];
#define LDA_V(K0) { _Pragma("unroll") for (int l = 0; l < 3; l++) {                      \
                      const int idx = l * 256 + t;                                       \
                      ar[l] = *(const float4*)(Asrc + (size_t)(idx >> 2) * CH + (K0) + (idx & 3) * 4); } }

    LDA_V(0); LDB_Z(0);
    STA_G(0); STB_G(0);
    LDA_V(16); LDB_Z(16);
    __syncthreads();

    for (int it = 0; it < 12; it++) {
        const int st = it & 1;
        if (it < 11) { STA_G(st ^ 1); STB_G(st ^ 1); }
        if (it < 10) { LDA_V(16 * (it + 2)); LDB_Z(16 * (it + 2)); }

        const unsigned* Bsl = Bs[st];
        const uint32_t aBase = sAs + (uint32_t)(st * 3840 * 4) + aoff;
#pragma unroll
        for (int h = 0; h < 2; h++) {
            const int kk = h * 8;
            unsigned af[3][4], bf[6][2];
#pragma unroll
            for (int mt = 0; mt < 3; mt++) {
                const int r0 = wm * 48 + mt * 16;
                ldsm_x4(af[mt], aBase + (uint32_t)((r0 * 20 + kk) * 4));
            }
#pragma unroll
            for (int nt = 0; nt < 6; nt++) {
                const int col = wn * 48 + nt * 8 + gid;
                bf[nt][0] = Bsl[(kk + tid4) * 104 + col];
                bf[nt][1] = Bsl[(kk + tid4 + 4) * 104 + col];
            }
#pragma unroll
            for (int mt = 0; mt < 3; mt++)
#pragma unroll
                for (int nt = 0; nt < 6; nt++)
                    mma_tf32(acc[mt][nt], af[mt], bf[nt]);
        }
        __syncthreads();
    }

#pragma unroll
    for (int mt = 0; mt < 3; mt++) {
        const int r0 = m0 + wm * 48 + mt * 16 + gid;
        const float b0 = beta[r0], b1 = beta[r0 + 8];
#pragma unroll
        for (int nt = 0; nt < 6; nt++) {
            const int pc = e * 192 + 96 * j + wn * 48 + nt * 8 + 2 * tid4;
            *(float2*)(vb + (size_t)r0 * 4608 + pc) =
                make_float2(acc[mt][nt][0] + b0, acc[mt][nt][1] + b0);
            *(float2*)(vb + (size_t)(r0 + 8) * 4608 + pc) =
                make_float2(acc[mt][nt][2] + b1, acc[mt][nt][3] + b1);
        }
    }
}

// ---------------------------------------------------------------------------
// K3: score partials v2. grid (12, H, B), 256 thr.
// ---------------------------------------------------------------------------
__global__ __launch_bounds__(256) void scores_kernel(const float* __restrict__ x)
{
    __shared__ float Xq[2][32][36], Zq[2][32][36], Xk[2][32][36], Zk[2][32][36];
    __shared__ float wbs[32];
    __shared__ float Sh[2][32][32];

    const int isl = blockIdx.x >> 1, ep = blockIdx.x & 1;
    const int h = blockIdx.y, b = blockIdx.z;
    const int i0 = isl * 32, e0 = ep * 12;
    const int t = threadIdx.x;
    const int wid = t >> 5, lane = t & 31;
    const int h32 = h * 32;

    const float* xb = x + (size_t)b * CH * NVOX;
    const float* zb = g_Z + (size_t)b * CH * NVOX;

    if (t < 32) wbs[t] = g_wb[i0 + t];

    const int li  = t >> 3;
    const int lc4 = (t & 7) << 2;

    const int ihalf = wid >> 1;
    const int sig = (wid & 1) * 32 + lane;
    const int ccg = sig >> 3;
    const int d0c = (sig & 7) << 2;

    float s[4][4];
#pragma unroll
    for (int a = 0; a < 4; a++)
#pragma unroll
        for (int q = 0; q < 4; q++) s[a][q] = 0.f;
    float dac = 0.f, wac = 0.f;

    const size_t rowoff = (size_t)(i0 + li) * NVOX;
    float4 rq, rzq, rk, rzk;
    {
        const int u = 576 * e0 + h32 + lc4;
        rq  = *(const float4*)(xb + rowoff + u);
        rzq = *(const float4*)(zb + rowoff + u);
        rk  = *(const float4*)(xb + rowoff + u + 192);
        rzk = *(const float4*)(zb + rowoff + u + 192);
    }
    *(float4*)&Xq[0][li][lc4] = rq;  *(float4*)&Zq[0][li][lc4] = rzq;
    *(float4*)&Xk[0][li][lc4] = rk;  *(float4*)&Zk[0][li][lc4] = rzk;
    __syncthreads();

    for (int e = 0; e < 12; e++) {
        const int cur = e & 1, nxt = cur ^ 1;
        if (e < 11) {
            const int u = 576 * (e0 + e + 1) + h32 + lc4;
            rq  = *(const float4*)(xb + rowoff + u);
            rzq = *(const float4*)(zb + rowoff + u);
            rk  = *(const float4*)(xb + rowoff + u + 192);
            rzk = *(const float4*)(zb + rowoff + u + 192);
        }
        if (wid < 4) {
            const int ib = ihalf * 16;
#pragma unroll
            for (int ii = 0; ii < 16; ii++) {
                const int i = ib + ii;
                const float4 zv = *(const float4*)&Zk[cur][i][d0c];
                const float q0 = Xq[cur][i][ccg];
                const float q1 = Xq[cur][i][ccg + 8];
                const float q2 = Xq[cur][i][ccg + 16];
                const float q3 = Xq[cur][i][ccg + 24];
                s[0][0] += q0 * zv.x; s[0][1] += q0 * zv.y; s[0][2] += q0 * zv.z; s[0][3] += q0 * zv.w;
                s[1][0] += q1 * zv.x; s[1][1] += q1 * zv.y; s[1][2] += q1 * zv.z; s[1][3] += q1 * zv.w;
                s[2][0] += q2 * zv.x; s[2][1] += q2 * zv.y; s[2][2] += q2 * zv.z; s[2][3] += q2 * zv.w;
                s[3][0] += q3 * zv.x; s[3][1] += q3 * zv.y; s[3][2] += q3 * zv.z; s[3][3] += q3 * zv.w;
            }
        } else if (wid == 4) {
#pragma unroll
            for (int i = 0; i < 32; i++) {
                const float xv = Xq[cur][i][lane];
                dac += xv * Zq[cur][i][lane];
                wac += wbs[i] * xv;
            }
        } else if (wid == 5) {
#pragma unroll
            for (int i = 0; i < 32; i++) {
                const float xv = Xk[cur][i][lane];
                dac += xv * Zk[cur][i][lane];
                wac += wbs[i] * xv;
            }
        }
        if (e < 11) {
            *(float4*)&Xq[nxt][li][lc4] = rq;  *(float4*)&Zq[nxt][li][lc4] = rzq;
            *(float4*)&Xk[nxt][li][lc4] = rk;  *(float4*)&Zk[nxt][li][lc4] = rzk;
        }
        __syncthreads();
    }

    if (wid < 4) {
#pragma unroll
        for (int a = 0; a < 4; a++)
            *(float4*)&Sh[ihalf][ccg + 8 * a][d0c] =
                make_float4(s[a][0], s[a][1], s[a][2], s[a][3]);
    }
    __syncthreads();

    float* sp = g_spart + (size_t)((b * HEADS + h) * 12 + blockIdx.x) * 1152;
    {
        const int eidx = t * 4;
        const float* s0 = &Sh[0][0][0];
        const float* s1 = &Sh[1][0][0];
        float4 a = *(const float4*)(s0 + eidx);
        float4 c = *(const float4*)(s1 + eidx);
        sp[eidx + 0] = a.x + c.x;
        sp[eidx + 1] = a.y + c.y;
        sp[eidx + 2] = a.z + c.z;
        sp[eidx + 3] = a.w + c.w;
    }
    if (wid == 4) { sp[1024 + lane] = dac; sp[1088 + lane] = wac; }
    if (wid == 5) { sp[1056 + lane] = dac; sp[1120 + lane] = wac; }
}

// ---------------------------------------------------------------------------
// K4: reduce partials, assemble S + bias terms, normalize, softmax -> attn
// ---------------------------------------------------------------------------
__global__ __launch_bounds__(256) void softmax_kernel(const float* __restrict__ temp)
{
    __shared__ float sS[1024];
    __shared__ float snq[32], snk[32], swq[32], swk[32];

    const int h = blockIdx.x, b = blockIdx.y;
    const int t = threadIdx.x;
    const float b2 = g_c[0];
    const float* sp = g_spart + (size_t)((b * HEADS + h) * 12) * 1152;

#pragma unroll
    for (int i = 0; i < 4; i++) {
        const int e = t + i * 256;
        float a = 0.f;
        for (int s = 0; s < 12; s++) a += sp[s * 1152 + e];
        sS[e] = a;
    }
    if (t < 64) {
        float d = 0.f, wv = 0.f;
        const int od = 1024 + t, ow = 1088 + t;
        for (int s = 0; s < 12; s++) { d += sp[s * 1152 + od]; wv += sp[s * 1152 + ow]; }
        const float n2 = d + 2.f * wv + 24.f * b2;
        const float r = fmaxf(sqrtf(fmaxf(n2, 0.f)), EPSN);
        if (t < 32) { snq[t] = r; swq[t] = wv; }
        else        { snk[t - 32] = r; swk[t - 32] = wv; }
    }
    __syncthreads();

    const int w = t >> 5, lane = t & 31;
    const float tv = temp[h];
    float* ab = g_attn + (size_t)((b * HEADS + h) * HD) * HD;

    for (int r = 0; r < 4; r++) {
        const int c = w * 4 + r;
        const float Sfull = sS[c * 32 + lane] + swq[c] + swk[lane] + 24.f * b2;
        float L = Sfull / (snq[c] * snk[lane]) * tv;
        float mx = L;
#pragma unroll
        for (int o = 16; o > 0; o >>= 1) mx = fmaxf(mx, __shfl_xor_sync(0xffffffffu, mx, o));
        const float ev = expf(L - mx);
        float sm = ev;
#pragma unroll
        for (int o = 16; o > 0; o >>= 1) sm += __shfl_xor_sync(0xffffffffu, sm, o);
        ab[c * 32 + lane] = ev / sm;
    }
}

// ---------------------------------------------------------------------------
// K5: M[b][o][h*32+d] = sum_cc pwT[cc*6+h][o] * attn[b,h,cc,d]
// ---------------------------------------------------------------------------
__global__ __launch_bounds__(192) void mmix_kernel()
{
    __shared__ float att[32][32];
    const int h = blockIdx.x, b = blockIdx.y;
    const int t = threadIdx.x;

    const float* ab = g_attn + (size_t)((b * HEADS + h) * HD) * HD;
    for (int e = t; e < 1024; e += 192) att[e >> 5][e & 31] = ab[e];
    __syncthreads();

    float s[32];
#pragma unroll
    for (int d = 0; d < 32; d++) s[d] = 0.f;

#pragma unroll 8
    for (int cc = 0; cc < 32; cc++) {
        const float v = g_pwT[(cc * HEADS + h) * CH + t];
#pragma unroll
        for (int d4 = 0; d4 < 8; d4++) {
            const float4 a = *(const float4*)&att[cc][d4 * 4];
            s[d4 * 4 + 0] += v * a.x;
            s[d4 * 4 + 1] += v * a.y;
            s[d4 * 4 + 2] += v * a.z;
            s[d4 * 4 + 3] += v * a.w;
        }
    }

    float* Mb = g_M + (size_t)b * CH * CH + t * CH + h * HD;
#pragma unroll
    for (int d = 0; d < 32; d++) Mb[d] = s[d];
}

// ---------------------------------------------------------------------------
// K6: y[b] = M[b] @ Vbuf[b]^T + proj_b.  BM=192, BN=96, 256 thr, 2 CTA/SM.
// A frags ldmatrix.x4; B stored n-major -> frags ldmatrix.x2.
// ---------------------------------------------------------------------------
__global__ __launch_bounds__(256, 2) void out_gemm(float* __restrict__ y,
                                                   const float* __restrict__ pbias)
{
    __shared__ unsigned As[2][192 * 20];
    __shared__ unsigned Bs[2][96 * 20];

    const int b  = blockIdx.z;
    const int n0 = blockIdx.x * 96;
    const int t  = threadIdx.x;
    const int wid = t >> 5, lane = t & 31;
    const int wm = wid & 3, wn = wid >> 2;
    const int gid = lane >> 2, tid4 = lane & 3;

    const float* Mb = g_M + (size_t)b * CH * CH;
    const float* vb = g_V + (size_t)b * NVOX * CH;
    float* yb = y + (size_t)b * CH * NVOX;

    const uint32_t sAs = smem_u32(As);
    const uint32_t sBs = smem_u32(Bs);
    const uint32_t aoff = (uint32_t)((((lane & 7) + ((lane >> 3) & 1) * 8) * 20 +
                                      ((lane >> 4) * 4)) * 4);
    const uint32_t boff = (uint32_t)(((lane & 7) * 20 + ((lane >> 3) & 1) * 4) * 4);

    float acc[3][6][4];
#pragma unroll
    for (int i = 0; i < 3; i++)
#pragma unroll
        for (int q = 0; q < 6; q++)
#pragma unroll
            for (int r = 0; r < 4; r++) acc[i][q][r] = 0.f;

    float4 ar[3], br[2];
#define LDA_O(K0) { _Pragma("unroll") for (int l = 0; l < 3; l++) {                      \
                      const int idx = l * 256 + t;                                       \
                      ar[l] = *(const float4*)(Mb + (size_t)(idx >> 2) * CH + (K0) + (idx & 3) * 4); } }
#define LDB_O(K0) { _Pragma("unroll") for (int l = 0; l < 2; l++) {                      \
                      const int idx = l * 256 + t;                                       \
                      if (idx < 384)                                                     \
                        br[l] = *(const float4*)(vb + (size_t)(n0 + (idx >> 2)) * CH + (K0) + (idx & 3) * 4); } }
#define STA_O(ST) { _Pragma("unroll") for (int l = 0; l < 3; l++) {                      \
                      const int idx = l * 256 + t;                                       \
                      unsigned* d = &As[ST][(idx >> 2) * 20 + (idx & 3) * 4];            \
                      d[0]=f2tf(ar[l].x); d[1]=f2tf(ar[l].y); d[2]=f2tf(ar[l].z); d[3]=f2tf(ar[l].w); } }
#define STB_O(ST) { _Pragma("unroll") for (int l = 0; l < 2; l++) {                      \
                      const int idx = l * 256 + t;                                       \
                      if (idx < 384) {                                                   \
                        unsigned* d = &Bs[ST][(idx >> 2) * 20 + (idx & 3) * 4];          \
                        d[0]=f2tf(br[l].x); d[1]=f2tf(br[l].y); d[2]=f2tf(br[l].z); d[3]=f2tf(br[l].w); } } }

    LDA_O(0); LDB_O(0);
    STA_O(0); STB_O(0);
    LDA_O(16); LDB_O(16);
    __syncthreads();

    for (int it = 0; it < 12; it++) {
        const int st = it & 1;
        if (it < 11) { STA_O(st ^ 1); STB_O(st ^ 1); }
        if (it < 10) { LDA_O(16 * (it + 2)); LDB_O(16 * (it + 2)); }

        const uint32_t aBase = sAs + (uint32_t)(st * 3840 * 4) + aoff;
        const uint32_t bBase = sBs + (uint32_t)(st * 1920 * 4) + boff;
#pragma unroll
        for (int h = 0; h < 2; h++) {
            const int kk = h * 8;
            unsigned af[3][4], bf[6][2];
#pragma unroll
            for (int mt = 0; mt < 3; mt++) {
                const int r0 = wm * 48 + mt * 16;
                ldsm_x4(af[mt], aBase + (uint32_t)((r0 * 20 + kk) * 4));
            }
#pragma unroll
            for (int nt = 0; nt < 6; nt++) {
                const int c0 = wn * 48 + nt * 8;
                ldsm_x2(bf[nt], bBase + (uint32_t)((c0 * 20 + kk) * 4));
            }
#pragma unroll
            for (int mt = 0; mt < 3; mt++)
#pragma unroll
                for (int nt = 0; nt < 6; nt++)
                    mma_tf32(acc[mt][nt], af[mt], bf[nt]);
        }
        __syncthreads();
    }

#pragma unroll
    for (int mt = 0; mt < 3; mt++) {
        const int r0 = wm * 48 + mt * 16 + gid;
        const float b0 = pbias[r0], b1 = pbias[r0 + 8];
#pragma unroll
        for (int nt = 0; nt < 6; nt++) {
            const int col = n0 + wn * 48 + nt * 8 + 2 * tid4;
            *(float2*)(yb + (size_t)r0 * NVOX + col) =
                make_float2(acc[mt][nt][0] + b0, acc[mt][nt][1] + b0);
            *(float2*)(yb + (size_t)(r0 + 8) * NVOX + col) =
                make_float2(acc[mt][nt][2] + b1, acc[mt][nt][3] + b1);
        }
    }
}

// ---------------------------------------------------------------------------
extern "C" void kernel_launch(void* const* d_in, const int* in_sizes, int n_in,
                              void* d_out, int out_size)
{
    const float* x      = (const float*)d_in[0];
    const float* qkv_w  = (const float*)d_in[1];
    const float* qkv_b  = (const float*)d_in[2];
    const float* temp   = (const float*)d_in[3];
    const float* proj_w = (const float*)d_in[4];
    const float* proj_b = (const float*)d_in[5];
    float* y = (float*)d_out;

    pre_kernel    <<<73, 256>>>(qkv_w, qkv_b, proj_w);

    z_gemm        <<<dim3(96, 1, BATCH), 256>>>(x);
    v_gemm        <<<dim3(48, 3, BATCH), 256>>>(x, qkv_w, qkv_b);
    scores_kernel <<<dim3(12, HEADS, BATCH), 256>>>(x);
    softmax_kernel<<<dim3(HEADS, BATCH), 256>>>(temp);
    mmix_kernel   <<<dim3(HEADS, BATCH), 192>>>();
    out_gemm      <<<dim3(144, 1, BATCH), 256>>>(y, proj_b);
}

// round 13
// speedup vs baseline: 1.4733x; 1.2166x over previous
#include <cuda_runtime.h>
#include <math.h>
#include <stdint.h>

#define BATCH  8
#define CH     192
#define C3     576
#define NVOX   13824       // 24*24*24
#define HEADS  6
#define HD     32
#define EPSN   1e-12f
#define TSTRIDE (CH * 4608)   // per-batch T size (fits in g_V slot)

// Scratch
__device__ float g_Z[(size_t)BATCH * CH * NVOX];     // Z = Gw @ X (only q/k cols valid)
__device__ float g_V[(size_t)BATCH * NVOX * CH];     // reused as T[b][o][e*192+c]
__device__ float g_Gw[CH * CH];
__device__ float g_wb[CH];
__device__ float g_pwT[CH * CH];
__device__ float g_msum[BATCH * CH];
__device__ float g_c[4];                             // [0] = b2
__device__ float g_spart[BATCH * HEADS * 12 * 1152];
__device__ float g_attn[BATCH * HEADS * HD * HD];
__device__ float g_M[BATCH * CH * CH];

// ---------------------------------------------------------------------------
__device__ __forceinline__ unsigned f2tf(float f) {
    unsigned u;
    asm("cvt.rna.tf32.f32 %0, %1;" : "=r"(u) : "f"(f));
    return u;
}
__device__ __forceinline__ void mma_tf32(float* c, const unsigned* a, const unsigned* b) {
    asm volatile(
        "mma.sync.aligned.m16n8k8.row.col.f32.tf32.tf32.f32 "
        "{%0,%1,%2,%3},{%4,%5,%6,%7},{%8,%9},{%0,%1,%2,%3};"
        : "+f"(c[0]), "+f"(c[1]), "+f"(c[2]), "+f"(c[3])
        : "r"(a[0]), "r"(a[1]), "r"(a[2]), "r"(a[3]), "r"(b[0]), "r"(b[1]));
}
__device__ __forceinline__ uint32_t smem_u32(const void* p) {
    uint32_t a;
    asm("{ .reg .u64 t; cvta.to.shared.u64 t, %1; cvt.u32.u64 %0, t; }" : "=r"(a) : "l"(p));
    return a;
}
__device__ __forceinline__ void ldsm_x4(unsigned* r, uint32_t addr) {
    asm volatile("ldmatrix.sync.aligned.m8n8.x4.shared.b16 {%0,%1,%2,%3}, [%4];"
        : "=r"(r[0]), "=r"(r[1]), "=r"(r[2]), "=r"(r[3]) : "r"(addr));
}
__device__ __forceinline__ void ldsm_x2(unsigned* r, uint32_t addr) {
    asm volatile("ldmatrix.sync.aligned.m8n8.x2.shared.b16 {%0,%1}, [%2];"
        : "=r"(r[0]), "=r"(r[1]) : "r"(addr));
}

// ---------------------------------------------------------------------------
// K0 merged prekernel: blocks 0..35 Gw tiles; 36..71 pwT tiles; 72 wb+b2.
// ---------------------------------------------------------------------------
__global__ __launch_bounds__(256) void pre_kernel(const float* __restrict__ w,
                                                  const float* __restrict__ beta,
                                                  const float* __restrict__ pw)
{
    __shared__ float sh[2112];
    const int bid = blockIdx.x;
    const int t = threadIdx.x;

    if (bid < 36) {
        float (*Wi)[33] = (float (*)[33])sh;
        float (*Wj)[33] = (float (*)[33])(sh + 1056);
        const int i0 = (bid % 6) * 32, j0 = (bid / 6) * 32;
        const int ti = t & 31, tj = (t >> 5) * 4;
        float acc[4] = {0.f, 0.f, 0.f, 0.f};
        for (int a0 = 0; a0 < C3; a0 += 32) {
            __syncthreads();
#pragma unroll
            for (int l = 0; l < 4; l++) {
                const int a = (t >> 5) + 8 * l, c = t & 31;
                Wi[a][c] = w[(a0 + a) * CH + i0 + c];
                Wj[a][c] = w[(a0 + a) * CH + j0 + c];
            }
            __syncthreads();
#pragma unroll
            for (int a = 0; a < 32; a++) {
                const float wi = Wi[a][ti];
#pragma unroll
                for (int r = 0; r < 4; r++) acc[r] += wi * Wj[a][tj + r];
            }
        }
#pragma unroll
        for (int r = 0; r < 4; r++) g_Gw[(i0 + ti) * CH + j0 + tj + r] = acc[r];
    } else if (bid < 72) {
        float (*tile)[33] = (float (*)[33])sh;
        const int bb = bid - 36;
        const int bx = (bb % 6) * 32, by = (bb / 6) * 32;
        const int tx = t & 31, ty = t >> 5;
#pragma unroll
        for (int l = 0; l < 4; l++)
            tile[ty + 8 * l][tx] = pw[(by + ty + 8 * l) * CH + bx + tx];
        __syncthreads();
#pragma unroll
        for (int l = 0; l < 4; l++)
            g_pwT[(bx + ty + 8 * l) * CH + by + tx] = tile[tx][ty + 8 * l];
    } else {
        if (t < CH) {
            float s = 0.f;
            for (int a = 0; a < C3; a++) s += beta[a] * w[a * CH + t];
            g_wb[t] = s;
        }
        if (t < 64) {
            float p = 0.f;
            for (int a = t; a < C3; a += 64) p += beta[a] * beta[a];
            sh[t] = p;
        }
        __syncthreads();
        if (t == 0) {
            float s = 0.f;
            for (int i = 0; i < 64; i++) s += sh[i];
            g_c[0] = s;
        }
    }
}

// ---------------------------------------------------------------------------
// K1: Z[b] = Gw @ X[b], columns 576e + 96j, j<4.
// BM=192, BN=96, BK=16, 256 thr, warp 48x48, 2 CTA/SM.
// ---------------------------------------------------------------------------
__global__ __launch_bounds__(256, 2) void z_gemm(const float* __restrict__ x)
{
    __shared__ unsigned As[2][192 * 20];
    __shared__ unsigned Bs[2][16 * 104];

    const int b = blockIdx.z;
    const int e = blockIdx.x >> 2, j = blockIdx.x & 3;
    const int n0 = 576 * e + 96 * j;
    const int t = threadIdx.x;
    const int wid = t >> 5, lane = t & 31;
    const int wm = wid & 3, wn = wid >> 2;
    const int gid = lane >> 2, tid4 = lane & 3;

    const float* bsrc = x + (size_t)b * CH * NVOX + n0;
    float* zb = g_Z + (size_t)b * CH * NVOX + n0;

    const uint32_t sAs = smem_u32(As);
    const uint32_t aoff = (uint32_t)((((lane & 7) + ((lane >> 3) & 1) * 8) * 20 +
                                      ((lane >> 4) * 4)) * 4);

    float acc[3][6][4];
#pragma unroll
    for (int i = 0; i < 3; i++)
#pragma unroll
        for (int q = 0; q < 6; q++)
#pragma unroll
            for (int r = 0; r < 4; r++) acc[i][q][r] = 0.f;

    float4 ar[3], br[2];
#define LDA_Z(K0) { _Pragma("unroll") for (int l = 0; l < 3; l++) {                      \
                      const int idx = l * 256 + t;                                       \
                      ar[l] = *(const float4*)(g_Gw + (idx >> 2) * CH + (K0) + (idx & 3) * 4); } }
#define LDB_Z(K0) { _Pragma("unroll") for (int l = 0; l < 2; l++) {                      \
                      const int idx = l * 256 + t;                                       \
                      if (idx < 384)                                                     \
                        br[l] = *(const float4*)(bsrc + (size_t)((K0) + idx / 24) * NVOX + (idx % 24) * 4); } }
#define STA_G(ST) { _Pragma("unroll") for (int l = 0; l < 3; l++) {                      \
                      const int idx = l * 256 + t;                                       \
                      unsigned* d = &As[ST][(idx >> 2) * 20 + (idx & 3) * 4];            \
                      d[0]=f2tf(ar[l].x); d[1]=f2tf(ar[l].y); d[2]=f2tf(ar[l].z); d[3]=f2tf(ar[l].w); } }
#define STB_G(ST) { _Pragma("unroll") for (int l = 0; l < 2; l++) {                      \
                      const int idx = l * 256 + t;                                       \
                      if (idx < 384) {                                                   \
                        unsigned* d = &Bs[ST][(idx / 24) * 104 + (idx % 24) * 4];        \
                        d[0]=f2tf(br[l].x); d[1]=f2tf(br[l].y); d[2]=f2tf(br[l].z); d[3]=f2tf(br[l].w); } } }

    LDA_Z(0); LDB_Z(0);
    STA_G(0); STB_G(0);
    LDA_Z(16); LDB_Z(16);
    __syncthreads();

    for (int it = 0; it < 12; it++) {
        const int st = it & 1;
        if (it < 11) { STA_G(st ^ 1); STB_G(st ^ 1); }
        if (it < 10) { LDA_Z(16 * (it + 2)); LDB_Z(16 * (it + 2)); }

        const unsigned* Bsl = Bs[st];
        const uint32_t aBase = sAs + (uint32_t)(st * 3840 * 4) + aoff;
#pragma unroll
        for (int h = 0; h < 2; h++) {
            const int kk = h * 8;
            unsigned af[3][4], bf[6][2];
#pragma unroll
            for (int mt = 0; mt < 3; mt++) {
                const int r0 = wm * 48 + mt * 16;
                ldsm_x4(af[mt], aBase + (uint32_t)((r0 * 20 + kk) * 4));
            }
#pragma unroll
            for (int nt = 0; nt < 6; nt++) {
                const int col = wn * 48 + nt * 8 + gid;
                bf[nt][0] = Bsl[(kk + tid4) * 104 + col];
                bf[nt][1] = Bsl[(kk + tid4 + 4) * 104 + col];
            }
#pragma unroll
            for (int mt = 0; mt < 3; mt++)
#pragma unroll
                for (int nt = 0; nt < 6; nt++)
                    mma_tf32(acc[mt][nt], af[mt], bf[nt]);
        }
        __syncthreads();
    }

#pragma unroll
    for (int mt = 0; mt < 3; mt++) {
        const int r0 = wm * 48 + mt * 16 + gid;
#pragma unroll
        for (int nt = 0; nt < 6; nt++) {
            const int col = wn * 48 + nt * 8 + 2 * tid4;
            *(float2*)(zb + (size_t)r0 * NVOX + col) = make_float2(acc[mt][nt][0], acc[mt][nt][1]);
            *(float2*)(zb + (size_t)(r0 + 8) * NVOX + col) = make_float2(acc[mt][nt][2], acc[mt][nt][3]);
        }
    }
}

// ---------------------------------------------------------------------------
// K3: score partials v2. grid (12, H, B), 256 thr.
// ---------------------------------------------------------------------------
__global__ __launch_bounds__(256) void scores_kernel(const float* __restrict__ x)
{
    __shared__ float Xq[2][32][36], Zq[2][32][36], Xk[2][32][36], Zk[2][32][36];
    __shared__ float wbs[32];
    __shared__ float Sh[2][32][32];

    const int isl = blockIdx.x >> 1, ep = blockIdx.x & 1;
    const int h = blockIdx.y, b = blockIdx.z;
    const int i0 = isl * 32, e0 = ep * 12;
    const int t = threadIdx.x;
    const int wid = t >> 5, lane = t & 31;
    const int h32 = h * 32;

    const float* xb = x + (size_t)b * CH * NVOX;
    const float* zb = g_Z + (size_t)b * CH * NVOX;

    if (t < 32) wbs[t] = g_wb[i0 + t];

    const int li  = t >> 3;
    const int lc4 = (t & 7) << 2;

    const int ihalf = wid >> 1;
    const int sig = (wid & 1) * 32 + lane;
    const int ccg = sig >> 3;
    const int d0c = (sig & 7) << 2;

    float s[4][4];
#pragma unroll
    for (int a = 0; a < 4; a++)
#pragma unroll
        for (int q = 0; q < 4; q++) s[a][q] = 0.f;
    float dac = 0.f, wac = 0.f;

    const size_t rowoff = (size_t)(i0 + li) * NVOX;
    float4 rq, rzq, rk, rzk;
    {
        const int u = 576 * e0 + h32 + lc4;
        rq  = *(const float4*)(xb + rowoff + u);
        rzq = *(const float4*)(zb + rowoff + u);
        rk  = *(const float4*)(xb + rowoff + u + 192);
        rzk = *(const float4*)(zb + rowoff + u + 192);
    }
    *(float4*)&Xq[0][li][lc4] = rq;  *(float4*)&Zq[0][li][lc4] = rzq;
    *(float4*)&Xk[0][li][lc4] = rk;  *(float4*)&Zk[0][li][lc4] = rzk;
    __syncthreads();

    for (int e = 0; e < 12; e++) {
        const int cur = e & 1, nxt = cur ^ 1;
        if (e < 11) {
            const int u = 576 * (e0 + e + 1) + h32 + lc4;
            rq  = *(const float4*)(xb + rowoff + u);
            rzq = *(const float4*)(zb + rowoff + u);
            rk  = *(const float4*)(xb + rowoff + u + 192);
            rzk = *(const float4*)(zb + rowoff + u + 192);
        }
        if (wid < 4) {
            const int ib = ihalf * 16;
#pragma unroll
            for (int ii = 0; ii < 16; ii++) {
                const int i = ib + ii;
                const float4 zv = *(const float4*)&Zk[cur][i][d0c];
                const float q0 = Xq[cur][i][ccg];
                const float q1 = Xq[cur][i][ccg + 8];
                const float q2 = Xq[cur][i][ccg + 16];
                const float q3 = Xq[cur][i][ccg + 24];
                s[0][0] += q0 * zv.x; s[0][1] += q0 * zv.y; s[0][2] += q0 * zv.z; s[0][3] += q0 * zv.w;
                s[1][0] += q1 * zv.x; s[1][1] += q1 * zv.y; s[1][2] += q1 * zv.z; s[1][3] += q1 * zv.w;
                s[2][0] += q2 * zv.x; s[2][1] += q2 * zv.y; s[2][2] += q2 * zv.z; s[2][3] += q2 * zv.w;
                s[3][0] += q3 * zv.x; s[3][1] += q3 * zv.y; s[3][2] += q3 * zv.z; s[3][3] += q3 * zv.w;
            }
        } else if (wid == 4) {
#pragma unroll
            for (int i = 0; i < 32; i++) {
                const float xv = Xq[cur][i][lane];
                dac += xv * Zq[cur][i][lane];
                wac += wbs[i] * xv;
            }
        } else if (wid == 5) {
#pragma unroll
            for (int i = 0; i < 32; i++) {
                const float xv = Xk[cur][i][lane];
                dac += xv * Zk[cur][i][lane];
                wac += wbs[i] * xv;
            }
        }
        if (e < 11) {
            *(float4*)&Xq[nxt][li][lc4] = rq;  *(float4*)&Zq[nxt][li][lc4] = rzq;
            *(float4*)&Xk[nxt][li][lc4] = rk;  *(float4*)&Zk[nxt][li][lc4] = rzk;
        }
        __syncthreads();
    }

    if (wid < 4) {
#pragma unroll
        for (int a = 0; a < 4; a++)
            *(float4*)&Sh[ihalf][ccg + 8 * a][d0c] =
                make_float4(s[a][0], s[a][1], s[a][2], s[a][3]);
    }
    __syncthreads();

    float* sp = g_spart + (size_t)((b * HEADS + h) * 12 + blockIdx.x) * 1152;
    {
        const int eidx = t * 4;
        const float* s0 = &Sh[0][0][0];
        const float* s1 = &Sh[1][0][0];
        float4 a = *(const float4*)(s0 + eidx);
        float4 c = *(const float4*)(s1 + eidx);
        sp[eidx + 0] = a.x + c.x;
        sp[eidx + 1] = a.y + c.y;
        sp[eidx + 2] = a.z + c.z;
        sp[eidx + 3] = a.w + c.w;
    }
    if (wid == 4) { sp[1024 + lane] = dac; sp[1088 + lane] = wac; }
    if (wid == 5) { sp[1056 + lane] = dac; sp[1120 + lane] = wac; }
}

// ---------------------------------------------------------------------------
// K4: reduce partials, assemble S + bias terms, normalize, softmax -> attn
// ---------------------------------------------------------------------------
__global__ __launch_bounds__(256) void softmax_kernel(const float* __restrict__ temp)
{
    __shared__ float sS[1024];
    __shared__ float snq[32], snk[32], swq[32], swk[32];

    const int h = blockIdx.x, b = blockIdx.y;
    const int t = threadIdx.x;
    const float b2 = g_c[0];
    const float* sp = g_spart + (size_t)((b * HEADS + h) * 12) * 1152;

#pragma unroll
    for (int i = 0; i < 4; i++) {
        const int e = t + i * 256;
        float a = 0.f;
        for (int s = 0; s < 12; s++) a += sp[s * 1152 + e];
        sS[e] = a;
    }
    if (t < 64) {
        float d = 0.f, wv = 0.f;
        const int od = 1024 + t, ow = 1088 + t;
        for (int s = 0; s < 12; s++) { d += sp[s * 1152 + od]; wv += sp[s * 1152 + ow]; }
        const float n2 = d + 2.f * wv + 24.f * b2;
        const float r = fmaxf(sqrtf(fmaxf(n2, 0.f)), EPSN);
        if (t < 32) { snq[t] = r; swq[t] = wv; }
        else        { snk[t - 32] = r; swk[t - 32] = wv; }
    }
    __syncthreads();

    const int w = t >> 5, lane = t & 31;
    const float tv = temp[h];
    float* ab = g_attn + (size_t)((b * HEADS + h) * HD) * HD;

    for (int r = 0; r < 4; r++) {
        const int c = w * 4 + r;
        const float Sfull = sS[c * 32 + lane] + swq[c] + swk[lane] + 24.f * b2;
        float L = Sfull / (snq[c] * snk[lane]) * tv;
        float mx = L;
#pragma unroll
        for (int o = 16; o > 0; o >>= 1) mx = fmaxf(mx, __shfl_xor_sync(0xffffffffu, mx, o));
        const float ev = expf(L - mx);
        float sm = ev;
#pragma unroll
        for (int o = 16; o > 0; o >>= 1) sm += __shfl_xor_sync(0xffffffffu, sm, o);
        ab[c * 32 + lane] = ev / sm;
    }
}

// ---------------------------------------------------------------------------
// K5: M[b][o][h*32+d] = sum_cc pwT[cc*6+h][o] * attn[b,h,cc,d]
// ---------------------------------------------------------------------------
__global__ __launch_bounds__(192) void mmix_kernel()
{
    __shared__ float att[32][32];
    const int h = blockIdx.x, b = blockIdx.y;
    const int t = threadIdx.x;

    const float* ab = g_attn + (size_t)((b * HEADS + h) * HD) * HD;
    for (int e = t; e < 1024; e += 192) att[e >> 5][e & 31] = ab[e];
    __syncthreads();

    float s[32];
#pragma unroll
    for (int d = 0; d < 32; d++) s[d] = 0.f;

#pragma unroll 8
    for (int cc = 0; cc < 32; cc++) {
        const float v = g_pwT[(cc * HEADS + h) * CH + t];
#pragma unroll
        for (int d4 = 0; d4 < 8; d4++) {
            const float4 a = *(const float4*)&att[cc][d4 * 4];
            s[d4 * 4 + 0] += v * a.x;
            s[d4 * 4 + 1] += v * a.y;
            s[d4 * 4 + 2] += v * a.z;
            s[d4 * 4 + 3] += v * a.w;
        }
    }

    float* Mb = g_M + (size_t)b * CH * CH + t * CH + h * HD;
#pragma unroll
    for (int d = 0; d < 32; d++) Mb[d] = s[d];
}

// K5b: msum[b][o] = sum_k M[o][k]
__global__ __launch_bounds__(192) void msum_kernel()
{
    const int b = blockIdx.x, t = threadIdx.x;
    const float* Mb = g_M + (size_t)b * CH * CH + (size_t)t * CH;
    float s = 0.f;
#pragma unroll 4
    for (int k = 0; k < CH; k += 4) {
        const float4 v = *(const float4*)(Mb + k);
        s += v.x + v.y + v.z + v.w;
    }
    g_msum[b * CH + t] = s;
}

// ---------------------------------------------------------------------------
// K6a (t_gemm): T[b][o][e*192+c] = sum_k M[o,k] * X[c, 576e+384+k]
// BM=192 (c rows, A=Xslice stride NVOX), BN=96 (o cols, B=M), K=192.
// grid (48 = 24e x 2 oB, 1, 8). Clone of proven out_gemm loop.
// ---------------------------------------------------------------------------
__global__ __launch_bounds__(256, 2) void t_gemm(const float* __restrict__ x)
{
    __shared__ unsigned As[2][192 * 20];
    __shared__ unsigned Bs[2][96 * 20];

    const int b  = blockIdx.z;
    const int e  = blockIdx.x >> 1;
    const int oB = (blockIdx.x & 1) * 96;
    const int t  = threadIdx.x;
    const int wid = t >> 5, lane = t & 31;
    const int wm = wid & 3, wn = wid >> 2;
    const int gid = lane >> 2, tid4 = lane & 3;

    const float* Asrc = x + (size_t)b * CH * NVOX + 576 * e + 384;
    const float* Bsrc = g_M + (size_t)b * CH * CH + (size_t)oB * CH;
    float* Tb = g_V + (size_t)b * TSTRIDE;

    const uint32_t sAs = smem_u32(As);
    const uint32_t sBs = smem_u32(Bs);
    const uint32_t aoff = (uint32_t)((((lane & 7) + ((lane >> 3) & 1) * 8) * 20 +
                                      ((lane >> 4) * 4)) * 4);
    const uint32_t boff = (uint32_t)(((lane & 7) * 20 + ((lane >> 3) & 1) * 4) * 4);

    float acc[3][6][4];
#pragma unroll
    for (int i = 0; i < 3; i++)
#pragma unroll
        for (int q = 0; q < 6; q++)
#pragma unroll
            for (int r = 0; r < 4; r++) acc[i][q][r] = 0.f;

    float4 ar[3], br[2];
#define LDA_T(K0) { _Pragma("unroll") for (int l = 0; l < 3; l++) {                      \
                      const int idx = l * 256 + t;                                       \
                      ar[l] = *(const float4*)(Asrc + (size_t)(idx >> 2) * NVOX + (K0) + (idx & 3) * 4); } }
#define LDB_T(K0) { _Pragma("unroll") for (int l = 0; l < 2; l++) {                      \
                      const int idx = l * 256 + t;                                       \
                      if (idx < 384)                                                     \
                        br[l] = *(const float4*)(Bsrc + (size_t)(idx >> 2) * CH + (K0) + (idx & 3) * 4); } }
#define STA_T(ST) { _Pragma("unroll") for (int l = 0; l < 3; l++) {                      \
                      const int idx = l * 256 + t;                                       \
                      unsigned* d = &As[ST][(idx >> 2) * 20 + (idx & 3) * 4];            \
                      d[0]=f2tf(ar[l].x); d[1]=f2tf(ar[l].y); d[2]=f2tf(ar[l].z); d[3]=f2tf(ar[l].w); } }
#define STB_T(ST) { _Pragma("unroll") for (int l = 0; l < 2; l++) {                      \
                      const int idx = l * 256 + t;                                       \
                      if (idx < 384) {                                                   \
                        unsigned* d = &Bs[ST][(idx >> 2) * 20 + (idx & 3) * 4];          \
                        d[0]=f2tf(br[l].x); d[1]=f2tf(br[l].y); d[2]=f2tf(br[l].z); d[3]=f2tf(br[l].w); } } }

    LDA_T(0); LDB_T(0);
    STA_T(0); STB_T(0);
    LDA_T(16); LDB_T(16);
    __syncthreads();

    for (int it = 0; it < 12; it++) {
        const int st = it & 1;
        if (it < 11) { STA_T(st ^ 1); STB_T(st ^ 1); }
        if (it < 10) { LDA_T(16 * (it + 2)); LDB_T(16 * (it + 2)); }

        const uint32_t aBase = sAs + (uint32_t)(st * 3840 * 4) + aoff;
        const uint32_t bBase = sBs + (uint32_t)(st * 1920 * 4) + boff;
#pragma unroll
        for (int h = 0; h < 2; h++) {
            const int kk = h * 8;
            unsigned af[3][4], bf[6][2];
#pragma unroll
            for (int mt = 0; mt < 3; mt++) {
                const int r0 = wm * 48 + mt * 16;
                ldsm_x4(af[mt], aBase + (uint32_t)((r0 * 20 + kk) * 4));
            }
#pragma unroll
            for (int nt = 0; nt < 6; nt++) {
                const int c0 = wn * 48 + nt * 8;
                ldsm_x2(bf[nt], bBase + (uint32_t)((c0 * 20 + kk) * 4));
            }
#pragma unroll
            for (int mt = 0; mt < 3; mt++)
#pragma unroll
                for (int nt = 0; nt < 6; nt++)
                    mma_tf32(acc[mt][nt], af[mt], bf[nt]);
        }
        __syncthreads();
    }

#pragma unroll
    for (int mt = 0; mt < 3; mt++) {
        const int c0 = wm * 48 + mt * 16 + gid;
#pragma unroll
        for (int nt = 0; nt < 6; nt++) {
            const int o0 = oB + wn * 48 + nt * 8 + 2 * tid4;
            float* p0 = Tb + (size_t)o0 * 4608 + e * 192;
            float* p1 = Tb + (size_t)(o0 + 1) * 4608 + e * 192;
            p0[c0]     = acc[mt][nt][0];
            p1[c0]     = acc[mt][nt][1];
            p0[c0 + 8] = acc[mt][nt][2];
            p1[c0 + 8] = acc[mt][nt][3];
        }
    }
}

// ---------------------------------------------------------------------------
// K6b (y_gemm): y[o][24a+e] = sum_c W[a,c]*T[o][e*192+c] + msum[o]*beta[a] + pbias[o]
// BM=192 (a rows, A=W), BN=96 cols (4 o x 24 e; B=T rows, c contiguous), K=192.
// grid (48 colblk, 3 m0, 8 b). Clone of proven out_gemm loop.
// ---------------------------------------------------------------------------
__global__ __launch_bounds__(256, 2) void y_gemm(float* __restrict__ y,
                                                 const float* __restrict__ qkv_w,
                                                 const float* __restrict__ qkv_b,
                                                 const float* __restrict__ pbias)
{
    __shared__ unsigned As[2][192 * 20];
    __shared__ unsigned Bs[2][96 * 20];

    const int b  = blockIdx.z;
    const int m0 = blockIdx.y * 192;
    const int cb = blockIdx.x;           // 0..47 -> o base = cb*4
    const int t  = threadIdx.x;
    const int wid = t >> 5, lane = t & 31;
    const int wm = wid & 3, wn = wid >> 2;
    const int gid = lane >> 2, tid4 = lane & 3;

    const float* Asrc = qkv_w + (size_t)m0 * CH;
    const float* Tb = g_V + (size_t)b * TSTRIDE + (size_t)cb * 4 * 4608;
    float* yb = y + (size_t)b * CH * NVOX;

    const uint32_t sAs = smem_u32(As);
    const uint32_t sBs = smem_u32(Bs);
    const uint32_t aoff = (uint32_t)((((lane & 7) + ((lane >> 3) & 1) * 8) * 20 +
                                      ((lane >> 4) * 4)) * 4);
    const uint32_t boff = (uint32_t)(((lane & 7) * 20 + ((lane >> 3) & 1) * 4) * 4);

    float acc[3][6][4];
#pragma unroll
    for (int i = 0; i < 3; i++)
#pragma unroll
        for (int q = 0; q < 6; q++)
#pragma unroll
            for (int r = 0; r < 4; r++) acc[i][q][r] = 0.f;

    float4 ar[3], br[2];
#define LDA_Y(K0) { _Pragma("unroll") for (int l = 0; l < 3; l++) {                      \
                      const int idx = l * 256 + t;                                       \
                      ar[l] = *(const float4*)(Asrc + (size_t)(idx >> 2) * CH + (K0) + (idx & 3) * 4); } }
#define LDB_Y(K0) { _Pragma("unroll") for (int l = 0; l < 2; l++) {                      \
                      const int idx = l * 256 + t;                                       \
                      if (idx < 384) {                                                   \
                        const int jj = idx >> 2;                                         \
                        br[l] = *(const float4*)(Tb + (size_t)(jj / 24) * 4608 +         \
                                                 (jj % 24) * 192 + (K0) + (idx & 3) * 4); } } }

    LDA_Y(0); LDB_Y(0);
    STA_T(0); STB_T(0);
    LDA_Y(16); LDB_Y(16);
    __syncthreads();

    for (int it = 0; it < 12; it++) {
        const int st = it & 1;
        if (it < 11) { STA_T(st ^ 1); STB_T(st ^ 1); }
        if (it < 10) { LDA_Y(16 * (it + 2)); LDB_Y(16 * (it + 2)); }

        const uint32_t aBase = sAs + (uint32_t)(st * 3840 * 4) + aoff;
        const uint32_t bBase = sBs + (uint32_t)(st * 1920 * 4) + boff;
#pragma unroll
        for (int h = 0; h < 2; h++) {
            const int kk = h * 8;
            unsigned af[3][4], bf[6][2];
#pragma unroll
            for (int mt = 0; mt < 3; mt++) {
                const int r0 = wm * 48 + mt * 16;
                ldsm_x4(af[mt], aBase + (uint32_t)((r0 * 20 + kk) * 4));
            }
#pragma unroll
            for (int nt = 0; nt < 6; nt++) {
                const int c0 = wn * 48 + nt * 8;
                ldsm_x2(bf[nt], bBase + (uint32_t)((c0 * 20 + kk) * 4));
            }
#pragma unroll
            for (int mt = 0; mt < 3; mt++)
#pragma unroll
                for (int nt = 0; nt < 6; nt++)
                    mma_tf32(acc[mt][nt], af[mt], bf[nt]);
        }
        __syncthreads();
    }

#pragma unroll
    for (int mt = 0; mt < 3; mt++) {
        const int r0 = wm * 48 + mt * 16 + gid;
        const int a0 = m0 + r0;
        const float be0 = qkv_b[a0], be1 = qkv_b[a0 + 8];
#pragma unroll
        for (int nt = 0; nt < 6; nt++) {
            const int j0 = wn * 48 + nt * 8 + 2 * tid4;
            const int o  = cb * 4 + j0 / 24;
            const int e  = j0 % 24;
            const float ms = g_msum[b * CH + o];
            const float pb = pbias[o];
            const float bias0 = ms * be0 + pb;
            const float bias1 = ms * be1 + pb;
            *(float2*)(yb + (size_t)o * NVOX + 24 * a0 + e) =
                make_float2(acc[mt][nt][0] + bias0, acc[mt][nt][1] + bias0);
            *(float2*)(yb + (size_t)o * NVOX + 24 * (a0 + 8) + e) =
                make_float2(acc[mt][nt][2] + bias1, acc[mt][nt][3] + bias1);
        }
    }
}

// ---------------------------------------------------------------------------
extern "C" void kernel_launch(void* const* d_in, const int* in_sizes, int n_in,
                              void* d_out, int out_size)
{
    const float* x      = (const float*)d_in[0];
    const float* qkv_w  = (const float*)d_in[1];
    const float* qkv_b  = (const float*)d_in[2];
    const float* temp   = (const float*)d_in[3];
    const float* proj_w = (const float*)d_in[4];
    const float* proj_b = (const float*)d_in[5];
    float* y = (float*)d_out;

    pre_kernel    <<<73, 256>>>(qkv_w, qkv_b, proj_w);
    z_gemm        <<<dim3(96, 1, BATCH), 256>>>(x);
    scores_kernel <<<dim3(12, HEADS, BATCH), 256>>>(x);
    softmax_kernel<<<dim3(HEADS, BATCH), 256>>>(temp);
    mmix_kernel   <<<dim3(HEADS, BATCH), 192>>>();
    msum_kernel   <<<BATCH, 192>>>();
    t_gemm        <<<dim3(48, 1, BATCH), 256>>>(x);
    y_gemm        <<<dim3(48, 3, BATCH), 256>>>(y, qkv_w, qkv_b, proj_b);
}